// round 1
// baseline (speedup 1.0000x reference)
#include <cuda_runtime.h>
#include <cuda_bf16.h>
#include <math.h>

// Problem constants
#define F_IN   256
#define NTREES 512
#define DEPTH  6
#define TDIM   3
#define BATCH  512
#define NCOLS  (NTREES * DEPTH)   // 3072

// Scratch (device globals; no runtime allocation allowed)
__device__ float g_W[F_IN * NCOLS];      // entmax weights, [256][3072]
__device__ float g_tl[NCOLS * BATCH];    // thresholded logits, TRANSPOSED [3072][512]

// ---------------------------------------------------------------------------
// Kernel 1: exact 1.5-entmax along axis 0 (F=256) for each of 3072 columns.
// One block (256 threads) per column. Bitonic sort + Hillis-Steele scans.
// ---------------------------------------------------------------------------
__global__ void entmax_kernel(const float* __restrict__ fa)
{
    const int col = blockIdx.x;      // 0..3071
    const int tid = threadIdx.x;     // 0..255

    __shared__ float s[256];     // sorted values (descending)
    __shared__ float cs[256];    // cumsum
    __shared__ float cs2[256];   // cumsum of squares
    __shared__ float tauv[256];  // tau per rank
    __shared__ float red[256];   // reduction scratch

    float z = fa[tid * NCOLS + col] * 0.5f;

    // max-reduce
    red[tid] = z;
    __syncthreads();
    #pragma unroll
    for (int st = 128; st > 0; st >>= 1) {
        if (tid < st) red[tid] = fmaxf(red[tid], red[tid + st]);
        __syncthreads();
    }
    const float zmax = red[0];
    __syncthreads();
    z -= zmax;

    s[tid] = z;
    __syncthreads();

    // bitonic sort, descending
    for (int k = 2; k <= 256; k <<= 1) {
        for (int j = k >> 1; j > 0; j >>= 1) {
            int ixj = tid ^ j;
            if (ixj > tid) {
                float a = s[tid];
                float b = s[ixj];
                bool desc = ((tid & k) == 0);
                if (desc ? (a < b) : (a > b)) {
                    s[tid] = b;
                    s[ixj] = a;
                }
            }
            __syncthreads();
        }
    }

    // inclusive scans of zs and zs^2 (Hillis-Steele)
    float v = s[tid];
    cs[tid]  = v;
    cs2[tid] = v * v;
    __syncthreads();
    #pragma unroll
    for (int off = 1; off < 256; off <<= 1) {
        float a = (tid >= off) ? cs[tid - off]  : 0.0f;
        float b = (tid >= off) ? cs2[tid - off] : 0.0f;
        __syncthreads();
        cs[tid]  += a;
        cs2[tid] += b;
        __syncthreads();
    }

    // tau per rank
    const float rho     = (float)(tid + 1);
    const float mean    = cs[tid] / rho;
    const float mean_sq = cs2[tid] / rho;
    const float ss      = rho * (mean_sq - mean * mean);
    const float delta   = (1.0f - ss) / rho;
    const float t_      = mean - sqrtf(fmaxf(delta, 0.0f));
    tauv[tid] = t_;

    // support size
    red[tid] = (t_ <= s[tid]) ? 1.0f : 0.0f;
    __syncthreads();
    #pragma unroll
    for (int st = 128; st > 0; st >>= 1) {
        if (tid < st) red[tid] += red[tid + st];
        __syncthreads();
    }
    const int kidx = (int)red[0] - 1;
    const float tau_star = tauv[kidx];

    const float r = fmaxf(z - tau_star, 0.0f);
    g_W[tid * NCOLS + col] = r * r;
}

// ---------------------------------------------------------------------------
// Kernel 2: fv = input[512x256] @ W[256x3072], fused threshold:
//   tl[n][b] = (fv[b][n] - thr[n]) * exp(-logT[n])   (stored transposed)
// Tiled 64x64x64, 256 threads, 4x4 micro-tiles.
// ---------------------------------------------------------------------------
#define BM 64
#define BN 64
#define BK 64

__global__ void gemm_thresh_kernel(const float* __restrict__ input,  // [512][256]
                                   const float* __restrict__ thr,    // [512][6]
                                   const float* __restrict__ ltemp)  // [512][6]
{
    __shared__ float As[BK][BM + 4];   // transposed A tile, padded stride 68
    __shared__ float Bs[BK][BN];       // B tile

    const int tx = threadIdx.x & 15;   // 0..15 -> batch micro position
    const int ty = threadIdx.x >> 4;   // 0..15 -> n micro position
    const int b0 = blockIdx.x * BM;
    const int n0 = blockIdx.y * BN;

    float acc[4][4];
    #pragma unroll
    for (int r = 0; r < 4; r++)
        #pragma unroll
        for (int c = 0; c < 4; c++) acc[r][c] = 0.0f;

    for (int k0 = 0; k0 < F_IN; k0 += BK) {
        // load A tile transposed: input[b0+m][k0+k] -> As[k][m]
        #pragma unroll
        for (int e = threadIdx.x; e < BM * BK; e += 256) {
            int m = e / BK;
            int k = e % BK;
            As[k][m] = input[(b0 + m) * F_IN + k0 + k];
        }
        // load B tile: g_W[k0+k][n0+n] -> Bs[k][n]
        #pragma unroll
        for (int e = threadIdx.x; e < BK * BN; e += 256) {
            int k = e / BN;
            int n = e % BN;
            Bs[k][n] = g_W[(k0 + k) * NCOLS + n0 + n];
        }
        __syncthreads();

        #pragma unroll
        for (int k = 0; k < BK; k++) {
            float4 af = *(const float4*)&As[k][tx * 4];
            float4 bf = *(const float4*)&Bs[k][ty * 4];
            float av[4] = {af.x, af.y, af.z, af.w};
            float bv[4] = {bf.x, bf.y, bf.z, bf.w};
            #pragma unroll
            for (int r = 0; r < 4; r++)
                #pragma unroll
                for (int c = 0; c < 4; c++)
                    acc[r][c] = fmaf(bv[r], av[c], acc[r][c]);
        }
        __syncthreads();
    }

    // epilogue: apply threshold/temperature, store transposed
    #pragma unroll
    for (int r = 0; r < 4; r++) {
        const int n = n0 + ty * 4 + r;
        const int t = n / DEPTH;
        const int d = n % DEPTH;
        const float th = thr[t * DEPTH + d];
        const float sc = expf(-ltemp[t * DEPTH + d]);
        float4 o;
        o.x = (acc[r][0] - th) * sc;
        o.y = (acc[r][1] - th) * sc;
        o.z = (acc[r][2] - th) * sc;
        o.w = (acc[r][3] - th) * sc;
        *(float4*)&g_tl[n * BATCH + b0 + tx * 4] = o;
    }
}

// ---------------------------------------------------------------------------
// Kernel 3: per (batch, tree): bins -> 64 leaf weights (doubling) -> out[3]
// Block: one tree x 128 batches. response tile (192 floats) in smem.
// ---------------------------------------------------------------------------
__global__ void leaf_kernel(const float* __restrict__ response,  // [512][3][64]
                            float* __restrict__ out)             // [512][1536]
{
    const int t      = blockIdx.x;        // tree
    const int bchunk = blockIdx.y;        // 0..3
    const int tid    = threadIdx.x;       // 0..127

    __shared__ float resp[TDIM * 64];
    for (int i = tid; i < TDIM * 64; i += 128)
        resp[i] = response[t * (TDIM * 64) + i];
    __syncthreads();

    const int b = bchunk * 128 + tid;

    float a[DEPTH], bbit[DEPTH];
    #pragma unroll
    for (int d = 0; d < DEPTH; d++) {
        float tl = g_tl[(t * DEPTH + d) * BATCH + b];
        float x = 0.5f * tl;
        // bit==0 side: clip(0.5 + 0.5*tl, -0.5, 1.5)
        a[d]    = fminf(fmaxf(0.5f + x, -0.5f), 1.5f);
        // bit==1 side: clip(0.5 - 0.5*tl, -0.5, 1.5)
        bbit[d] = fminf(fmaxf(0.5f - x, -0.5f), 1.5f);
    }

    float w[64];
    w[0] = 1.0f;
    #pragma unroll
    for (int d = 0; d < DEPTH; d++) {
        const int sz = 1 << d;
        #pragma unroll
        for (int i = sz - 1; i >= 0; i--) {
            w[i + sz] = w[i] * bbit[d];
            w[i]      = w[i] * a[d];
        }
    }

    float o0 = 0.0f, o1 = 0.0f, o2 = 0.0f;
    #pragma unroll
    for (int c = 0; c < 64; c++) {
        float wc = w[c];
        o0 = fmaf(wc, resp[c],       o0);
        o1 = fmaf(wc, resp[64 + c],  o1);
        o2 = fmaf(wc, resp[128 + c], o2);
    }

    float* op = out + (size_t)b * (NTREES * TDIM) + t * TDIM;
    op[0] = o0;
    op[1] = o1;
    op[2] = o2;
}

// ---------------------------------------------------------------------------
extern "C" void kernel_launch(void* const* d_in, const int* in_sizes, int n_in,
                              void* d_out, int out_size)
{
    const float* input    = (const float*)d_in[0];  // [512][256]
    const float* fa       = (const float*)d_in[1];  // [256][3072]
    const float* thr      = (const float*)d_in[2];  // [512][6]
    const float* ltemp    = (const float*)d_in[3];  // [512][6]
    const float* response = (const float*)d_in[4];  // [512][3][64]
    float* out = (float*)d_out;                     // [512][1536]

    entmax_kernel<<<NCOLS, 256>>>(fa);

    dim3 g2(BATCH / BM, NCOLS / BN);
    gemm_thresh_kernel<<<g2, 256>>>(input, thr, ltemp);

    dim3 g3(NTREES, BATCH / 128);
    leaf_kernel<<<g3, 128>>>(response, out);
}

// round 2
// speedup vs baseline: 1.0429x; 1.0429x over previous
#include <cuda_runtime.h>
#include <cuda_bf16.h>
#include <math.h>

// Problem constants
#define F_IN   256
#define NTREES 512
#define DEPTH  6
#define TDIM   3
#define BATCH  512
#define NCOLS  (NTREES * DEPTH)   // 3072

// Scratch (device globals; no runtime allocation allowed)
__device__ float g_Wt[NCOLS * F_IN];     // entmax weights TRANSPOSED [3072][256]
__device__ float g_tl[NCOLS * BATCH];    // thresholded logits, TRANSPOSED [3072][512]

// ---------------------------------------------------------------------------
// Kernel 1: exact 1.5-entmax along axis 0 (F=256) per column, via Newton on
//   g(tau) = sum max(z - tau, 0)^2 - 1  (convex, decreasing; monotone
//   convergence from tau0 = max(z) - 1). One warp per column, 8 vals/thread.
// Block = 256 threads = 8 warps handles 32 columns (4 per warp).
// ---------------------------------------------------------------------------
#define CPB 32   // columns per block

__global__ void entmax_kernel(const float* __restrict__ fa)
{
    __shared__ float s[256][CPB + 1];   // pad 33 -> conflict-free column reads

    const int c0   = blockIdx.x * CPB;
    const int tid  = threadIdx.x;
    const int lane = tid & 31;
    const int w    = tid >> 5;

    // coalesced tile load (0.5 * fa)
    #pragma unroll
    for (int i = 0; i < CPB; i++) {
        int e = tid + i * 256;
        int r = e >> 5;
        int c = e & 31;
        s[r][c] = 0.5f * fa[r * NCOLS + c0 + c];
    }
    __syncthreads();

    #pragma unroll
    for (int cc = 0; cc < 4; cc++) {
        const int c = w * 4 + cc;

        float z[8];
        #pragma unroll
        for (int j = 0; j < 8; j++) z[j] = s[lane + 32 * j][c];

        // column max (warp butterfly)
        float m = z[0];
        #pragma unroll
        for (int j = 1; j < 8; j++) m = fmaxf(m, z[j]);
        #pragma unroll
        for (int off = 16; off > 0; off >>= 1)
            m = fmaxf(m, __shfl_xor_sync(0xffffffffu, m, off));
        #pragma unroll
        for (int j = 0; j < 8; j++) z[j] -= m;

        // Newton: tau0 = -1 (since max(z)=0); monotone from below
        float tau = -1.0f;
        #pragma unroll 4
        for (int it = 0; it < 20; it++) {
            float s1 = 0.0f, s2 = 0.0f;
            #pragma unroll
            for (int j = 0; j < 8; j++) {
                float d = fmaxf(z[j] - tau, 0.0f);
                s1 += d;
                s2 = fmaf(d, d, s2);
            }
            #pragma unroll
            for (int off = 16; off > 0; off >>= 1) {
                s1 += __shfl_xor_sync(0xffffffffu, s1, off);
                s2 += __shfl_xor_sync(0xffffffffu, s2, off);
            }
            tau += (s2 - 1.0f) / (2.0f * s1);
        }

        // coalesced transposed store: g_Wt[col][row]
        #pragma unroll
        for (int j = 0; j < 8; j++) {
            float d = fmaxf(z[j] - tau, 0.0f);
            g_Wt[(c0 + c) * F_IN + lane + 32 * j] = d * d;
        }
    }
}

// ---------------------------------------------------------------------------
// Kernel 2: fv = input[512x256] @ W[256x3072]  (W stored transposed [n][k]),
// fused threshold: tl[n][b] = (fv[b][n] - thr[n]) * exp(-logT[n]).
// 128x64x32 tiles, 256 threads, 8x4 micro-tiles.
// ---------------------------------------------------------------------------
#define BM 128
#define BN 64
#define BK 32

__global__ void gemm_thresh_kernel(const float* __restrict__ input,  // [512][256]
                                   const float* __restrict__ thr,    // [512][6]
                                   const float* __restrict__ ltemp)  // [512][6]
{
    __shared__ float As[BK][BM + 4];   // [32][132]
    __shared__ float Bs[BK][BN + 4];   // [32][68]

    const int tm = threadIdx.x & 15;   // 0..15 -> 8 batches each
    const int tn = threadIdx.x >> 4;   // 0..15 -> 4 cols each
    const int b0 = blockIdx.x * BM;
    const int n0 = blockIdx.y * BN;

    float acc[8][4];
    #pragma unroll
    for (int r = 0; r < 8; r++)
        #pragma unroll
        for (int c = 0; c < 4; c++) acc[r][c] = 0.0f;

    for (int k0 = 0; k0 < F_IN; k0 += BK) {
        // A tile: input[b0+m][k0+k] -> As[k][m]   (128x32, 16 elems/thread)
        #pragma unroll
        for (int i = 0; i < (BM * BK) / 256; i++) {
            int e = threadIdx.x + i * 256;
            int mm = e >> 5;
            int kk = e & 31;
            As[kk][mm] = input[(b0 + mm) * F_IN + k0 + kk];
        }
        // B tile: g_Wt[n0+n][k0+k] -> Bs[k][n]    (64x32, 8 elems/thread)
        #pragma unroll
        for (int i = 0; i < (BN * BK) / 256; i++) {
            int e = threadIdx.x + i * 256;
            int nn = e >> 5;
            int kk = e & 31;
            Bs[kk][nn] = g_Wt[(n0 + nn) * F_IN + k0 + kk];
        }
        __syncthreads();

        #pragma unroll
        for (int k = 0; k < BK; k++) {
            float4 a0 = *(const float4*)&As[k][tm * 8];
            float4 a1 = *(const float4*)&As[k][tm * 8 + 4];
            float4 bf = *(const float4*)&Bs[k][tn * 4];
            float av[8] = {a0.x, a0.y, a0.z, a0.w, a1.x, a1.y, a1.z, a1.w};
            float bv[4] = {bf.x, bf.y, bf.z, bf.w};
            #pragma unroll
            for (int r = 0; r < 8; r++)
                #pragma unroll
                for (int c = 0; c < 4; c++)
                    acc[r][c] = fmaf(av[r], bv[c], acc[r][c]);
        }
        __syncthreads();
    }

    // epilogue: threshold + temperature, store transposed tl[n][b]
    #pragma unroll
    for (int c = 0; c < 4; c++) {
        const int n = n0 + tn * 4 + c;
        const int t = n / DEPTH;
        const int d = n % DEPTH;
        const float th = thr[t * DEPTH + d];
        const float sc = expf(-ltemp[t * DEPTH + d]);
        float4 o0, o1;
        o0.x = (acc[0][c] - th) * sc;
        o0.y = (acc[1][c] - th) * sc;
        o0.z = (acc[2][c] - th) * sc;
        o0.w = (acc[3][c] - th) * sc;
        o1.x = (acc[4][c] - th) * sc;
        o1.y = (acc[5][c] - th) * sc;
        o1.z = (acc[6][c] - th) * sc;
        o1.w = (acc[7][c] - th) * sc;
        float* dst = &g_tl[n * BATCH + b0 + tm * 8];
        *(float4*)dst       = o0;
        *(float4*)(dst + 4) = o1;
    }
}

// ---------------------------------------------------------------------------
// Kernel 3: per (batch, tree): bins -> 64 leaf weights (doubling) -> out[3]
// ---------------------------------------------------------------------------
__global__ void leaf_kernel(const float* __restrict__ response,  // [512][3][64]
                            float* __restrict__ out)             // [512][1536]
{
    const int t      = blockIdx.x;
    const int bchunk = blockIdx.y;
    const int tid    = threadIdx.x;

    __shared__ float resp[TDIM * 64];
    for (int i = tid; i < TDIM * 64; i += 128)
        resp[i] = response[t * (TDIM * 64) + i];
    __syncthreads();

    const int b = bchunk * 128 + tid;

    float a[DEPTH], bbit[DEPTH];
    #pragma unroll
    for (int d = 0; d < DEPTH; d++) {
        float tl = g_tl[(t * DEPTH + d) * BATCH + b];
        float x = 0.5f * tl;
        a[d]    = fminf(fmaxf(0.5f + x, -0.5f), 1.5f);
        bbit[d] = fminf(fmaxf(0.5f - x, -0.5f), 1.5f);
    }

    float w[64];
    w[0] = 1.0f;
    #pragma unroll
    for (int d = 0; d < DEPTH; d++) {
        const int sz = 1 << d;
        #pragma unroll
        for (int i = sz - 1; i >= 0; i--) {
            w[i + sz] = w[i] * bbit[d];
            w[i]      = w[i] * a[d];
        }
    }

    float o0 = 0.0f, o1 = 0.0f, o2 = 0.0f;
    #pragma unroll
    for (int c = 0; c < 64; c++) {
        float wc = w[c];
        o0 = fmaf(wc, resp[c],       o0);
        o1 = fmaf(wc, resp[64 + c],  o1);
        o2 = fmaf(wc, resp[128 + c], o2);
    }

    float* op = out + (size_t)b * (NTREES * TDIM) + t * TDIM;
    op[0] = o0;
    op[1] = o1;
    op[2] = o2;
}

// ---------------------------------------------------------------------------
extern "C" void kernel_launch(void* const* d_in, const int* in_sizes, int n_in,
                              void* d_out, int out_size)
{
    const float* input    = (const float*)d_in[0];  // [512][256]
    const float* fa       = (const float*)d_in[1];  // [256][3072]
    const float* thr      = (const float*)d_in[2];  // [512][6]
    const float* ltemp    = (const float*)d_in[3];  // [512][6]
    const float* response = (const float*)d_in[4];  // [512][3][64]
    float* out = (float*)d_out;                     // [512][1536]

    entmax_kernel<<<NCOLS / CPB, 256>>>(fa);

    dim3 g2(BATCH / BM, NCOLS / BN);
    gemm_thresh_kernel<<<g2, 256>>>(input, thr, ltemp);

    dim3 g3(NTREES, BATCH / 128);
    leaf_kernel<<<g3, 128>>>(response, out);
}

// round 5
// speedup vs baseline: 2.0649x; 1.9799x over previous
#include <cuda_runtime.h>
#include <cuda_bf16.h>
#include <math.h>
#include <stdint.h>

// Problem constants
#define F_IN   256
#define NTREES 512
#define DEPTH  6
#define TDIM   3
#define BATCH  512
#define NCOLS  (NTREES * DEPTH)   // 3072
#define KP     512                // hi||lo concatenated K

// Scratch (device globals)
__device__ __nv_bfloat16 g_A[NCOLS * KP];   // W^T split: [n][k]=hi, [n][256+k]=lo
__device__ __nv_bfloat16 g_B[BATCH * KP];   // input split: [b][k]=hi, [b][256+k]=lo
__device__ float g_tl[NCOLS * BATCH];       // thresholded logits [3072][512]

// ---------------------------------------------------------------------------
// Portable tensor-path helpers (sm_80+ baseline; NO tcgen05)
// ---------------------------------------------------------------------------
__device__ __forceinline__ uint32_t smem_u32(const void* p) {
    uint32_t a;
    asm("{ .reg .u64 t; cvta.to.shared.u64 t, %1; cvt.u32.u64 %0, t; }" : "=r"(a) : "l"(p));
    return a;
}
__device__ __forceinline__ void cpa16(uint32_t dst, const void* src) {
    asm volatile("cp.async.cg.shared.global [%0], [%1], 16;" :: "r"(dst), "l"(src));
}
__device__ __forceinline__ void ldsm4(uint32_t* r, uint32_t addr) {
    asm volatile("ldmatrix.sync.aligned.m8n8.x4.shared.b16 {%0,%1,%2,%3}, [%4];"
                 : "=r"(r[0]), "=r"(r[1]), "=r"(r[2]), "=r"(r[3]) : "r"(addr));
}
__device__ __forceinline__ void mma16816(float* c, const uint32_t* a,
                                         uint32_t b0, uint32_t b1) {
    asm volatile(
        "mma.sync.aligned.m16n8k16.row.col.f32.bf16.bf16.f32 "
        "{%0,%1,%2,%3}, {%4,%5,%6,%7}, {%8,%9}, {%0,%1,%2,%3};"
        : "+f"(c[0]), "+f"(c[1]), "+f"(c[2]), "+f"(c[3])
        : "r"(a[0]), "r"(a[1]), "r"(a[2]), "r"(a[3]), "r"(b0), "r"(b1));
}
// 128B-row XOR swizzle: 16B chunk index ^= (row & 7)
__device__ __forceinline__ uint32_t swz(uint32_t base, int row, int kbyte) {
    uint32_t off = (uint32_t)(row * 128 + kbyte);
    return base + (off ^ ((off >> 3) & 0x70));
}

// ---------------------------------------------------------------------------
// Kernel 0: split input fp32 -> bf16 hi/lo into g_B [512][512] (hi||lo)
// ---------------------------------------------------------------------------
__global__ void split_input_kernel(const float* __restrict__ input)
{
    int i = blockIdx.x * blockDim.x + threadIdx.x;   // 0..32767 (float4 units)
    int b = i >> 6;
    int r = i & 63;
    float4 v = ((const float4*)input)[i];
    float vals[4] = {v.x, v.y, v.z, v.w};
    __nv_bfloat16 hi[4], lo[4];
    #pragma unroll
    for (int j = 0; j < 4; j++) {
        hi[j] = __float2bfloat16(vals[j]);
        lo[j] = __float2bfloat16(vals[j] - __bfloat162float(hi[j]));
    }
    __nv_bfloat162* ph = (__nv_bfloat162*)g_B + b * 256 + r * 2;
    __nv_bfloat162* pl = ph + 128;
    ph[0] = __nv_bfloat162{hi[0], hi[1]};
    ph[1] = __nv_bfloat162{hi[2], hi[3]};
    pl[0] = __nv_bfloat162{lo[0], lo[1]};
    pl[1] = __nv_bfloat162{lo[2], lo[3]};
}

// ---------------------------------------------------------------------------
// Kernel 1: exact 1.5-entmax per column (Newton on g(tau)=sum relu(z-tau)^2-1,
// convex => monotone convergence). 2 columns per warp, interleaved for ILP.
// Block = 256 threads = 16 columns. Emits bf16 hi/lo into g_A.
// ---------------------------------------------------------------------------
#define CPB 16

__global__ void entmax_kernel(const float* __restrict__ fa)
{
    __shared__ float s[256][CPB + 1];

    const int c0   = blockIdx.x * CPB;
    const int tid  = threadIdx.x;
    const int lane = tid & 31;
    const int w    = tid >> 5;

    #pragma unroll
    for (int i = 0; i < CPB; i++) {
        int e = tid + i * 256;
        int r = e >> 4;
        int c = e & 15;
        s[r][c] = 0.5f * fa[r * NCOLS + c0 + c];
    }
    __syncthreads();

    const int cA = 2 * w, cB = 2 * w + 1;

    float zA[8], zB[8];
    #pragma unroll
    for (int j = 0; j < 8; j++) {
        zA[j] = s[lane + 32 * j][cA];
        zB[j] = s[lane + 32 * j][cB];
    }

    float mA = zA[0], mB = zB[0];
    #pragma unroll
    for (int j = 1; j < 8; j++) { mA = fmaxf(mA, zA[j]); mB = fmaxf(mB, zB[j]); }
    #pragma unroll
    for (int off = 16; off > 0; off >>= 1) {
        mA = fmaxf(mA, __shfl_xor_sync(0xffffffffu, mA, off));
        mB = fmaxf(mB, __shfl_xor_sync(0xffffffffu, mB, off));
    }
    #pragma unroll
    for (int j = 0; j < 8; j++) { zA[j] -= mA; zB[j] -= mB; }

    float tauA = -1.0f, tauB = -1.0f;
    #pragma unroll 4
    for (int it = 0; it < 16; it++) {
        float s1A = 0.0f, s2A = 0.0f, s1B = 0.0f, s2B = 0.0f;
        #pragma unroll
        for (int j = 0; j < 8; j++) {
            float dA = fmaxf(zA[j] - tauA, 0.0f);
            float dB = fmaxf(zB[j] - tauB, 0.0f);
            s1A += dA; s2A = fmaf(dA, dA, s2A);
            s1B += dB; s2B = fmaf(dB, dB, s2B);
        }
        #pragma unroll
        for (int off = 16; off > 0; off >>= 1) {
            s1A += __shfl_xor_sync(0xffffffffu, s1A, off);
            s2A += __shfl_xor_sync(0xffffffffu, s2A, off);
            s1B += __shfl_xor_sync(0xffffffffu, s1B, off);
            s2B += __shfl_xor_sync(0xffffffffu, s2B, off);
        }
        tauA += (s2A - 1.0f) / (2.0f * s1A);
        tauB += (s2B - 1.0f) / (2.0f * s1B);
    }

    #pragma unroll
    for (int j = 0; j < 8; j++) {
        float dA = fmaxf(zA[j] - tauA, 0.0f);
        float dB = fmaxf(zB[j] - tauB, 0.0f);
        float wA = dA * dA, wB = dB * dB;
        __nv_bfloat16 hA = __float2bfloat16(wA);
        __nv_bfloat16 hB = __float2bfloat16(wB);
        int iA = (c0 + cA) * KP + lane + 32 * j;
        int iB = (c0 + cB) * KP + lane + 32 * j;
        g_A[iA]       = hA;
        g_A[iA + 256] = __float2bfloat16(wA - __bfloat162float(hA));
        g_A[iB]       = hB;
        g_A[iB + 256] = __float2bfloat16(wB - __bfloat162float(hB));
    }
}

// ---------------------------------------------------------------------------
// Kernel 2: HMMA bf16 GEMM  D[n,b] = sum_{k<512} A[n,k]*B[b,k]
// (hi||lo split => exact fp32 product to ~2^-16), fused threshold epilogue.
// CTA: M=128(n) x N=64(b), 8 warps of 32x32, K chunks of 64, double-buffered
// cp.async, XOR-swizzled smem, ldmatrix.x4 operand loads.
// ---------------------------------------------------------------------------
#define CK 64
#define NKC (KP / CK)    // 8

#define SA0 0
#define SA1 16384
#define SB0 32768
#define SB1 40960
#define SM_TOTAL 49152

__device__ __forceinline__ void load_A_chunk(uint32_t sbase, int n0, int kc, int tid)
{
    #pragma unroll
    for (int j = 0; j < 4; j++) {
        int e = tid + j * 256;
        int row = e >> 3;
        int ch  = e & 7;
        cpa16(swz(sbase, row, ch * 16),
              g_A + (size_t)(n0 + row) * KP + kc * CK + ch * 8);
    }
}
__device__ __forceinline__ void load_B_chunk(uint32_t sbase, int b0, int kc, int tid)
{
    #pragma unroll
    for (int j = 0; j < 2; j++) {
        int e = tid + j * 256;
        int row = e >> 3;
        int ch  = e & 7;
        cpa16(swz(sbase, row, ch * 16),
              g_B + (size_t)(b0 + row) * KP + kc * CK + ch * 8);
    }
}

__global__ void __launch_bounds__(256, 1)
gemm_hmma_kernel(const float* __restrict__ thr,
                 const float* __restrict__ ltemp)
{
    extern __shared__ char smem[];
    const uint32_t sb = smem_u32(smem);
    const int tid  = threadIdx.x;
    const int lane = tid & 31;
    const int wid  = tid >> 5;
    const int wm   = wid >> 1;        // 0..3  (M warp)
    const int wn   = wid & 1;         // 0..1  (N warp)

    const int n0 = blockIdx.x * 128;
    const int b0 = blockIdx.y * 64;

    const uint32_t sA[2] = {sb + SA0, sb + SA1};
    const uint32_t sB[2] = {sb + SB0, sb + SB1};

    float acc[2][4][4];
    #pragma unroll
    for (int mi = 0; mi < 2; mi++)
        #pragma unroll
        for (int ni = 0; ni < 4; ni++)
            #pragma unroll
            for (int q = 0; q < 4; q++) acc[mi][ni][q] = 0.0f;

    // prefetch chunk 0
    load_A_chunk(sA[0], n0, 0, tid);
    load_B_chunk(sB[0], b0, 0, tid);
    asm volatile("cp.async.commit_group;");

    const int lane15 = lane & 15;
    const int khalf  = (lane >> 4) * 16;   // byte offset of k-half

    int buf = 0;
    for (int kc = 0; kc < NKC; kc++) {
        if (kc + 1 < NKC) {
            load_A_chunk(sA[buf ^ 1], n0, kc + 1, tid);
            load_B_chunk(sB[buf ^ 1], b0, kc + 1, tid);
            asm volatile("cp.async.commit_group;");
            asm volatile("cp.async.wait_group 1;");
        } else {
            asm volatile("cp.async.wait_group 0;");
        }
        __syncthreads();

        #pragma unroll
        for (int ks = 0; ks < 4; ks++) {
            const int kbyte = ks * 32 + khalf;
            uint32_t a0[4], a1[4], bq0[4], bq1[4];
            ldsm4(a0,  swz(sA[buf], wm * 32 + lane15,      kbyte));
            ldsm4(a1,  swz(sA[buf], wm * 32 + 16 + lane15, kbyte));
            ldsm4(bq0, swz(sB[buf], wn * 32 + lane15,      kbyte));
            ldsm4(bq1, swz(sB[buf], wn * 32 + 16 + lane15, kbyte));

            mma16816(acc[0][0], a0, bq0[0], bq0[2]);
            mma16816(acc[0][1], a0, bq0[1], bq0[3]);
            mma16816(acc[0][2], a0, bq1[0], bq1[2]);
            mma16816(acc[0][3], a0, bq1[1], bq1[3]);
            mma16816(acc[1][0], a1, bq0[0], bq0[2]);
            mma16816(acc[1][1], a1, bq0[1], bq0[3]);
            mma16816(acc[1][2], a1, bq1[0], bq1[2]);
            mma16816(acc[1][3], a1, bq1[1], bq1[3]);
        }
        __syncthreads();
        buf ^= 1;
    }

    // epilogue: threshold + temperature, store g_tl[n][b]
    const int qr = lane >> 2;          // 0..7
    const int qc = (lane & 3) * 2;     // 0,2,4,6
    #pragma unroll
    for (int mi = 0; mi < 2; mi++) {
        const int nr0 = n0 + wm * 32 + mi * 16 + qr;
        const int nr1 = nr0 + 8;
        const int t0 = nr0 / DEPTH, d0 = nr0 % DEPTH;
        const int t1 = nr1 / DEPTH, d1 = nr1 % DEPTH;
        const float th0 = thr[t0 * DEPTH + d0];
        const float sc0 = expf(-ltemp[t0 * DEPTH + d0]);
        const float th1 = thr[t1 * DEPTH + d1];
        const float sc1 = expf(-ltemp[t1 * DEPTH + d1]);
        #pragma unroll
        for (int ni = 0; ni < 4; ni++) {
            const int bc = b0 + wn * 32 + ni * 8 + qc;
            float2 v0, v1;
            v0.x = (acc[mi][ni][0] - th0) * sc0;
            v0.y = (acc[mi][ni][1] - th0) * sc0;
            v1.x = (acc[mi][ni][2] - th1) * sc1;
            v1.y = (acc[mi][ni][3] - th1) * sc1;
            *(float2*)&g_tl[(size_t)nr0 * BATCH + bc] = v0;
            *(float2*)&g_tl[(size_t)nr1 * BATCH + bc] = v1;
        }
    }
}

// ---------------------------------------------------------------------------
// Kernel 3: per (batch, tree): bins -> 64 leaf weights -> out[3]
// ---------------------------------------------------------------------------
__global__ void leaf_kernel(const float* __restrict__ response,  // [512][3][64]
                            float* __restrict__ out)             // [512][1536]
{
    const int t      = blockIdx.x;
    const int bchunk = blockIdx.y;
    const int tid    = threadIdx.x;

    __shared__ float resp[TDIM * 64];
    for (int i = tid; i < TDIM * 64; i += 128)
        resp[i] = response[t * (TDIM * 64) + i];
    __syncthreads();

    const int b = bchunk * 128 + tid;

    float a[DEPTH], bbit[DEPTH];
    #pragma unroll
    for (int d = 0; d < DEPTH; d++) {
        float tl = g_tl[(size_t)(t * DEPTH + d) * BATCH + b];
        float x = 0.5f * tl;
        a[d]    = fminf(fmaxf(0.5f + x, -0.5f), 1.5f);
        bbit[d] = fminf(fmaxf(0.5f - x, -0.5f), 1.5f);
    }

    float w[64];
    w[0] = 1.0f;
    #pragma unroll
    for (int d = 0; d < DEPTH; d++) {
        const int sz = 1 << d;
        #pragma unroll
        for (int i = sz - 1; i >= 0; i--) {
            w[i + sz] = w[i] * bbit[d];
            w[i]      = w[i] * a[d];
        }
    }

    float o0 = 0.0f, o1 = 0.0f, o2 = 0.0f;
    #pragma unroll
    for (int c = 0; c < 64; c++) {
        float wc = w[c];
        o0 = fmaf(wc, resp[c],       o0);
        o1 = fmaf(wc, resp[64 + c],  o1);
        o2 = fmaf(wc, resp[128 + c], o2);
    }

    float* op = out + (size_t)b * (NTREES * TDIM) + t * TDIM;
    op[0] = o0;
    op[1] = o1;
    op[2] = o2;
}

// ---------------------------------------------------------------------------
extern "C" void kernel_launch(void* const* d_in, const int* in_sizes, int n_in,
                              void* d_out, int out_size)
{
    const float* input    = (const float*)d_in[0];  // [512][256]
    const float* fa       = (const float*)d_in[1];  // [256][3072]
    const float* thr      = (const float*)d_in[2];  // [512][6]
    const float* ltemp    = (const float*)d_in[3];  // [512][6]
    const float* response = (const float*)d_in[4];  // [512][3][64]
    float* out = (float*)d_out;                     // [512][1536]

    cudaFuncSetAttribute(gemm_hmma_kernel,
                         cudaFuncAttributeMaxDynamicSharedMemorySize, SM_TOTAL);

    split_input_kernel<<<BATCH * F_IN / (4 * 256), 256>>>(input);
    entmax_kernel<<<NCOLS / CPB, 256>>>(fa);

    dim3 g2(NCOLS / 128, BATCH / 64);
    gemm_hmma_kernel<<<g2, 256, SM_TOTAL>>>(thr, ltemp);

    dim3 g3(NTREES, BATCH / 128);
    leaf_kernel<<<g3, 128>>>(response, out);
}

// round 6
// speedup vs baseline: 2.5345x; 1.2274x over previous
#include <cuda_runtime.h>
#include <cuda_bf16.h>
#include <math.h>
#include <stdint.h>

// Problem constants
#define F_IN   256
#define NTREES 512
#define DEPTH  6
#define TDIM   3
#define BATCH  512
#define NCOLS  (NTREES * DEPTH)   // 3072
#define KP     768                // hi || lo || hi (A)  /  hi || hi || lo (B)

// Scratch (device globals)
__device__ __nv_bfloat16 g_A[NCOLS * KP];   // W^T: [n][k]=hi, [n][256+k]=lo, [n][512+k]=hi
__device__ __nv_bfloat16 g_B[BATCH * KP];   // in : [b][k]=hi, [b][256+k]=hi, [b][512+k]=lo
__device__ float g_tl[NCOLS * BATCH];       // thresholded logits [3072][512]

// ---------------------------------------------------------------------------
// Portable tensor-path helpers (sm_80+ baseline; NO tcgen05 — ptxas targets
// plain sm_103 in this harness)
// ---------------------------------------------------------------------------
__device__ __forceinline__ uint32_t smem_u32(const void* p) {
    uint32_t a;
    asm("{ .reg .u64 t; cvta.to.shared.u64 t, %1; cvt.u32.u64 %0, t; }" : "=r"(a) : "l"(p));
    return a;
}
__device__ __forceinline__ void cpa16(uint32_t dst, const void* src) {
    asm volatile("cp.async.cg.shared.global [%0], [%1], 16;" :: "r"(dst), "l"(src));
}
__device__ __forceinline__ void ldsm4(uint32_t* r, uint32_t addr) {
    asm volatile("ldmatrix.sync.aligned.m8n8.x4.shared.b16 {%0,%1,%2,%3}, [%4];"
                 : "=r"(r[0]), "=r"(r[1]), "=r"(r[2]), "=r"(r[3]) : "r"(addr));
}
__device__ __forceinline__ void mma16816(float* c, const uint32_t* a,
                                         uint32_t b0, uint32_t b1) {
    asm volatile(
        "mma.sync.aligned.m16n8k16.row.col.f32.bf16.bf16.f32 "
        "{%0,%1,%2,%3}, {%4,%5,%6,%7}, {%8,%9}, {%0,%1,%2,%3};"
        : "+f"(c[0]), "+f"(c[1]), "+f"(c[2]), "+f"(c[3])
        : "r"(a[0]), "r"(a[1]), "r"(a[2]), "r"(a[3]), "r"(b0), "r"(b1));
}
// 128B-row XOR swizzle: 16B chunk index ^= (row & 7)
__device__ __forceinline__ uint32_t swz(uint32_t base, int row, int kbyte) {
    uint32_t off = (uint32_t)(row * 128 + kbyte);
    return base + (off ^ ((off >> 3) & 0x70));
}

// ---------------------------------------------------------------------------
// Kernel 0: split input fp32 -> bf16 into g_B [512][768] = [hi || hi || lo]
// ---------------------------------------------------------------------------
__global__ void split_input_kernel(const float* __restrict__ input)
{
    int i = blockIdx.x * blockDim.x + threadIdx.x;   // float4 units over [512][256]
    int b = i >> 6;
    int r = i & 63;
    float4 v = ((const float4*)input)[i];
    float vals[4] = {v.x, v.y, v.z, v.w};
    __nv_bfloat16 hi[4], lo[4];
    #pragma unroll
    for (int j = 0; j < 4; j++) {
        hi[j] = __float2bfloat16(vals[j]);
        lo[j] = __float2bfloat16(vals[j] - __bfloat162float(hi[j]));
    }
    __nv_bfloat162 h0{hi[0], hi[1]}, h1{hi[2], hi[3]};
    __nv_bfloat162 l0{lo[0], lo[1]}, l1{lo[2], lo[3]};
    __nv_bfloat162* row = (__nv_bfloat162*)g_B + b * (KP / 2) + r * 2;
    row[0]       = h0;  row[1]       = h1;   // seg 0: hi
    row[128]     = h0;  row[129]     = h1;   // seg 1: hi
    row[256]     = l0;  row[257]     = l1;   // seg 2: lo
}

// ---------------------------------------------------------------------------
// Kernel 1: exact 1.5-entmax per column (Newton on g(tau)=sum relu(z-tau)^2-1,
// convex => monotone convergence). 2 columns per warp, interleaved for ILP.
// Block = 256 threads = 16 columns. Emits [hi || lo || hi] rows of g_A.
// ---------------------------------------------------------------------------
#define CPB 16

__global__ void entmax_kernel(const float* __restrict__ fa)
{
    __shared__ float s[256][CPB + 1];

    const int c0   = blockIdx.x * CPB;
    const int tid  = threadIdx.x;
    const int lane = tid & 31;
    const int w    = tid >> 5;

    #pragma unroll
    for (int i = 0; i < CPB; i++) {
        int e = tid + i * 256;
        int r = e >> 4;
        int c = e & 15;
        s[r][c] = 0.5f * fa[r * NCOLS + c0 + c];
    }
    __syncthreads();

    const int cA = 2 * w, cB = 2 * w + 1;

    float zA[8], zB[8];
    #pragma unroll
    for (int j = 0; j < 8; j++) {
        zA[j] = s[lane + 32 * j][cA];
        zB[j] = s[lane + 32 * j][cB];
    }

    float mA = zA[0], mB = zB[0];
    #pragma unroll
    for (int j = 1; j < 8; j++) { mA = fmaxf(mA, zA[j]); mB = fmaxf(mB, zB[j]); }
    #pragma unroll
    for (int off = 16; off > 0; off >>= 1) {
        mA = fmaxf(mA, __shfl_xor_sync(0xffffffffu, mA, off));
        mB = fmaxf(mB, __shfl_xor_sync(0xffffffffu, mB, off));
    }
    #pragma unroll
    for (int j = 0; j < 8; j++) { zA[j] -= mA; zB[j] -= mB; }

    float tauA = -1.0f, tauB = -1.0f;
    #pragma unroll 4
    for (int it = 0; it < 16; it++) {
        float s1A = 0.0f, s2A = 0.0f, s1B = 0.0f, s2B = 0.0f;
        #pragma unroll
        for (int j = 0; j < 8; j++) {
            float dA = fmaxf(zA[j] - tauA, 0.0f);
            float dB = fmaxf(zB[j] - tauB, 0.0f);
            s1A += dA; s2A = fmaf(dA, dA, s2A);
            s1B += dB; s2B = fmaf(dB, dB, s2B);
        }
        #pragma unroll
        for (int off = 16; off > 0; off >>= 1) {
            s1A += __shfl_xor_sync(0xffffffffu, s1A, off);
            s2A += __shfl_xor_sync(0xffffffffu, s2A, off);
            s1B += __shfl_xor_sync(0xffffffffu, s1B, off);
            s2B += __shfl_xor_sync(0xffffffffu, s2B, off);
        }
        tauA += (s2A - 1.0f) / (2.0f * s1A);
        tauB += (s2B - 1.0f) / (2.0f * s1B);
    }

    #pragma unroll
    for (int j = 0; j < 8; j++) {
        float dA = fmaxf(zA[j] - tauA, 0.0f);
        float dB = fmaxf(zB[j] - tauB, 0.0f);
        float wA = dA * dA, wB = dB * dB;
        __nv_bfloat16 hA = __float2bfloat16(wA);
        __nv_bfloat16 hB = __float2bfloat16(wB);
        int iA = (c0 + cA) * KP + lane + 32 * j;
        int iB = (c0 + cB) * KP + lane + 32 * j;
        g_A[iA]       = hA;                                       // seg 0: hi
        g_A[iA + 256] = __float2bfloat16(wA - __bfloat162float(hA)); // seg 1: lo
        g_A[iA + 512] = hA;                                       // seg 2: hi
        g_A[iB]       = hB;
        g_A[iB + 256] = __float2bfloat16(wB - __bfloat162float(hB));
        g_A[iB + 512] = hB;
    }
}

// ---------------------------------------------------------------------------
// Kernel 2: HMMA bf16 GEMM  D[n,b] = sum_{k<768} A[n,k]*B[b,k]
//   = hiA.hiB + loA.hiB + hiA.loB  (drops only loA.loB ~ 2^-18)
// CTA: M=128(n) x N=64(b), 8 warps of 32x32, K chunks of 64, double-buffered
// cp.async, XOR-swizzled smem, ldmatrix.x4 operand loads. Fused threshold.
// ---------------------------------------------------------------------------
#define CK 64
#define NKC (KP / CK)    // 12

#define SA0 0
#define SA1 16384
#define SB0 32768
#define SB1 40960
#define SM_TOTAL 49152

__device__ __forceinline__ void load_A_chunk(uint32_t sbase, int n0, int kc, int tid)
{
    #pragma unroll
    for (int j = 0; j < 4; j++) {
        int e = tid + j * 256;
        int row = e >> 3;
        int ch  = e & 7;
        cpa16(swz(sbase, row, ch * 16),
              g_A + (size_t)(n0 + row) * KP + kc * CK + ch * 8);
    }
}
__device__ __forceinline__ void load_B_chunk(uint32_t sbase, int b0, int kc, int tid)
{
    #pragma unroll
    for (int j = 0; j < 2; j++) {
        int e = tid + j * 256;
        int row = e >> 3;
        int ch  = e & 7;
        cpa16(swz(sbase, row, ch * 16),
              g_B + (size_t)(b0 + row) * KP + kc * CK + ch * 8);
    }
}

__global__ void __launch_bounds__(256, 1)
gemm_hmma_kernel(const float* __restrict__ thr,
                 const float* __restrict__ ltemp)
{
    extern __shared__ char smem[];
    const uint32_t sb = smem_u32(smem);
    const int tid  = threadIdx.x;
    const int lane = tid & 31;
    const int wid  = tid >> 5;
    const int wm   = wid >> 1;        // 0..3  (M warp)
    const int wn   = wid & 1;         // 0..1  (N warp)

    const int n0 = blockIdx.x * 128;
    const int b0 = blockIdx.y * 64;

    const uint32_t sA[2] = {sb + SA0, sb + SA1};
    const uint32_t sB[2] = {sb + SB0, sb + SB1};

    float acc[2][4][4];
    #pragma unroll
    for (int mi = 0; mi < 2; mi++)
        #pragma unroll
        for (int ni = 0; ni < 4; ni++)
            #pragma unroll
            for (int q = 0; q < 4; q++) acc[mi][ni][q] = 0.0f;

    load_A_chunk(sA[0], n0, 0, tid);
    load_B_chunk(sB[0], b0, 0, tid);
    asm volatile("cp.async.commit_group;");

    const int lane15 = lane & 15;
    const int khalf  = (lane >> 4) * 16;   // byte offset of k-half

    int buf = 0;
    for (int kc = 0; kc < NKC; kc++) {
        if (kc + 1 < NKC) {
            load_A_chunk(sA[buf ^ 1], n0, kc + 1, tid);
            load_B_chunk(sB[buf ^ 1], b0, kc + 1, tid);
            asm volatile("cp.async.commit_group;");
            asm volatile("cp.async.wait_group 1;");
        } else {
            asm volatile("cp.async.wait_group 0;");
        }
        __syncthreads();

        #pragma unroll
        for (int ks = 0; ks < 4; ks++) {
            const int kbyte = ks * 32 + khalf;
            uint32_t a0[4], a1[4], bq0[4], bq1[4];
            ldsm4(a0,  swz(sA[buf], wm * 32 + lane15,      kbyte));
            ldsm4(a1,  swz(sA[buf], wm * 32 + 16 + lane15, kbyte));
            ldsm4(bq0, swz(sB[buf], wn * 32 + lane15,      kbyte));
            ldsm4(bq1, swz(sB[buf], wn * 32 + 16 + lane15, kbyte));

            mma16816(acc[0][0], a0, bq0[0], bq0[2]);
            mma16816(acc[0][1], a0, bq0[1], bq0[3]);
            mma16816(acc[0][2], a0, bq1[0], bq1[2]);
            mma16816(acc[0][3], a0, bq1[1], bq1[3]);
            mma16816(acc[1][0], a1, bq0[0], bq0[2]);
            mma16816(acc[1][1], a1, bq0[1], bq0[3]);
            mma16816(acc[1][2], a1, bq1[0], bq1[2]);
            mma16816(acc[1][3], a1, bq1[1], bq1[3]);
        }
        __syncthreads();
        buf ^= 1;
    }

    // epilogue: threshold + temperature, store g_tl[n][b]
    const int qr = lane >> 2;          // 0..7
    const int qc = (lane & 3) * 2;     // 0,2,4,6
    #pragma unroll
    for (int mi = 0; mi < 2; mi++) {
        const int nr0 = n0 + wm * 32 + mi * 16 + qr;
        const int nr1 = nr0 + 8;
        const int t0 = nr0 / DEPTH, d0 = nr0 % DEPTH;
        const int t1 = nr1 / DEPTH, d1 = nr1 % DEPTH;
        const float th0 = thr[t0 * DEPTH + d0];
        const float sc0 = expf(-ltemp[t0 * DEPTH + d0]);
        const float th1 = thr[t1 * DEPTH + d1];
        const float sc1 = expf(-ltemp[t1 * DEPTH + d1]);
        #pragma unroll
        for (int ni = 0; ni < 4; ni++) {
            const int bc = b0 + wn * 32 + ni * 8 + qc;
            float2 v0, v1;
            v0.x = (acc[mi][ni][0] - th0) * sc0;
            v0.y = (acc[mi][ni][1] - th0) * sc0;
            v1.x = (acc[mi][ni][2] - th1) * sc1;
            v1.y = (acc[mi][ni][3] - th1) * sc1;
            *(float2*)&g_tl[(size_t)nr0 * BATCH + bc] = v0;
            *(float2*)&g_tl[(size_t)nr1 * BATCH + bc] = v1;
        }
    }
}

// ---------------------------------------------------------------------------
// Kernel 3: per (batch, tree): bins -> out[3].
// Spill-free: build only the 16-leaf product of depths 0..3 in registers;
// depths 4,5 folded analytically in the epilogue:
//   out_ch = sum_{j<4} q_j * sum_{c<16} w16[c] * resp[ch][16*j + c]
//   q = {a4*a5, b4*a5, a4*b5, b4*b5}   (j = bit4 + 2*bit5)
// ---------------------------------------------------------------------------
__global__ void __launch_bounds__(128, 8)
leaf_kernel(const float* __restrict__ response,  // [512][3][64]
            float* __restrict__ out)             // [512][1536]
{
    const int t      = blockIdx.x;
    const int bchunk = blockIdx.y;
    const int tid    = threadIdx.x;

    __shared__ float resp[TDIM * 64];
    for (int i = tid; i < TDIM * 64; i += 128)
        resp[i] = response[t * (TDIM * 64) + i];
    __syncthreads();

    const int b = bchunk * 128 + tid;

    float a[DEPTH], bbit[DEPTH];
    #pragma unroll
    for (int d = 0; d < DEPTH; d++) {
        float tl = g_tl[(size_t)(t * DEPTH + d) * BATCH + b];
        float x = 0.5f * tl;
        a[d]    = fminf(fmaxf(0.5f + x, -0.5f), 1.5f);   // bit == 0
        bbit[d] = fminf(fmaxf(0.5f - x, -0.5f), 1.5f);   // bit == 1
    }

    // 16-leaf product over depths 0..3
    float w16[16];
    w16[0] = 1.0f;
    #pragma unroll
    for (int d = 0; d < 4; d++) {
        const int sz = 1 << d;
        #pragma unroll
        for (int i = sz - 1; i >= 0; i--) {
            w16[i + sz] = w16[i] * bbit[d];
            w16[i]      = w16[i] * a[d];
        }
    }

    const float q[4] = { a[4] * a[5], bbit[4] * a[5],
                         a[4] * bbit[5], bbit[4] * bbit[5] };

    float o0 = 0.0f, o1 = 0.0f, o2 = 0.0f;
    #pragma unroll
    for (int j = 0; j < 4; j++) {
        float s0 = 0.0f, s1 = 0.0f, s2 = 0.0f;
        #pragma unroll
        for (int c = 0; c < 16; c++) {
            float wc = w16[c];
            s0 = fmaf(wc, resp[      j * 16 + c], s0);
            s1 = fmaf(wc, resp[ 64 + j * 16 + c], s1);
            s2 = fmaf(wc, resp[128 + j * 16 + c], s2);
        }
        o0 = fmaf(q[j], s0, o0);
        o1 = fmaf(q[j], s1, o1);
        o2 = fmaf(q[j], s2, o2);
    }

    float* op = out + (size_t)b * (NTREES * TDIM) + t * TDIM;
    op[0] = o0;
    op[1] = o1;
    op[2] = o2;
}

// ---------------------------------------------------------------------------
extern "C" void kernel_launch(void* const* d_in, const int* in_sizes, int n_in,
                              void* d_out, int out_size)
{
    const float* input    = (const float*)d_in[0];  // [512][256]
    const float* fa       = (const float*)d_in[1];  // [256][3072]
    const float* thr      = (const float*)d_in[2];  // [512][6]
    const float* ltemp    = (const float*)d_in[3];  // [512][6]
    const float* response = (const float*)d_in[4];  // [512][3][64]
    float* out = (float*)d_out;                     // [512][1536]

    cudaFuncSetAttribute(gemm_hmma_kernel,
                         cudaFuncAttributeMaxDynamicSharedMemorySize, SM_TOTAL);

    split_input_kernel<<<BATCH * F_IN / (4 * 256), 256>>>(input);
    entmax_kernel<<<NCOLS / CPB, 256>>>(fa);

    dim3 g2(NCOLS / 128, BATCH / 64);
    gemm_hmma_kernel<<<g2, 256, SM_TOTAL>>>(thr, ltemp);

    dim3 g3(NTREES, BATCH / 128);
    leaf_kernel<<<g3, 128>>>(response, out);
}

// round 7
// speedup vs baseline: 2.6250x; 1.0357x over previous
#include <cuda_runtime.h>
#include <cuda_bf16.h>
#include <math.h>
#include <stdint.h>

// Problem constants
#define F_IN   256
#define NTREES 512
#define DEPTH  6
#define TDIM   3
#define BATCH  512
#define NCOLS  (NTREES * DEPTH)   // 3072
#define KP     768                // hi || lo || hi (A)  /  hi || hi || lo (B)

// Scratch (device globals)
__device__ __nv_bfloat16 g_A[NCOLS * KP];   // W^T: [n][k]=hi, [n][256+k]=lo, [n][512+k]=hi
__device__ __nv_bfloat16 g_B[BATCH * KP];   // in : [b][k]=hi, [b][256+k]=hi, [b][512+k]=lo
__device__ float g_tl[NCOLS * BATCH];       // thresholded logits [3072][512]

// ---------------------------------------------------------------------------
// Portable tensor-path helpers (sm_80+ baseline; ptxas targets plain sm_103)
// ---------------------------------------------------------------------------
__device__ __forceinline__ uint32_t smem_u32(const void* p) {
    uint32_t a;
    asm("{ .reg .u64 t; cvta.to.shared.u64 t, %1; cvt.u32.u64 %0, t; }" : "=r"(a) : "l"(p));
    return a;
}
__device__ __forceinline__ void cpa16(uint32_t dst, const void* src) {
    asm volatile("cp.async.cg.shared.global [%0], [%1], 16;" :: "r"(dst), "l"(src));
}
__device__ __forceinline__ void ldsm4(uint32_t* r, uint32_t addr) {
    asm volatile("ldmatrix.sync.aligned.m8n8.x4.shared.b16 {%0,%1,%2,%3}, [%4];"
                 : "=r"(r[0]), "=r"(r[1]), "=r"(r[2]), "=r"(r[3]) : "r"(addr));
}
__device__ __forceinline__ void mma16816(float* c, const uint32_t* a,
                                         uint32_t b0, uint32_t b1) {
    asm volatile(
        "mma.sync.aligned.m16n8k16.row.col.f32.bf16.bf16.f32 "
        "{%0,%1,%2,%3}, {%4,%5,%6,%7}, {%8,%9}, {%0,%1,%2,%3};"
        : "+f"(c[0]), "+f"(c[1]), "+f"(c[2]), "+f"(c[3])
        : "r"(a[0]), "r"(a[1]), "r"(a[2]), "r"(a[3]), "r"(b0), "r"(b1));
}
// 128B-row XOR swizzle: 16B chunk index ^= (row & 7)
__device__ __forceinline__ uint32_t swz(uint32_t base, int row, int kbyte) {
    uint32_t off = (uint32_t)(row * 128 + kbyte);
    return base + (off ^ ((off >> 3) & 0x70));
}

// ---------------------------------------------------------------------------
// Kernel 0: split input fp32 -> bf16 into g_B [512][768] = [hi || hi || lo]
// ---------------------------------------------------------------------------
__global__ void split_input_kernel(const float* __restrict__ input)
{
    int i = blockIdx.x * blockDim.x + threadIdx.x;   // float4 units over [512][256]
    int b = i >> 6;
    int r = i & 63;
    float4 v = ((const float4*)input)[i];
    float vals[4] = {v.x, v.y, v.z, v.w};
    __nv_bfloat16 hi[4], lo[4];
    #pragma unroll
    for (int j = 0; j < 4; j++) {
        hi[j] = __float2bfloat16(vals[j]);
        lo[j] = __float2bfloat16(vals[j] - __bfloat162float(hi[j]));
    }
    __nv_bfloat162 h0{hi[0], hi[1]}, h1{hi[2], hi[3]};
    __nv_bfloat162 l0{lo[0], lo[1]}, l1{lo[2], lo[3]};
    __nv_bfloat162* row = (__nv_bfloat162*)g_B + b * (KP / 2) + r * 2;
    row[0]   = h0;  row[1]   = h1;   // seg 0: hi
    row[128] = h0;  row[129] = h1;   // seg 1: hi
    row[256] = l0;  row[257] = l1;   // seg 2: lo
}

// ---------------------------------------------------------------------------
// Kernel 1: exact 1.5-entmax per column (Newton on g(tau)=sum relu(z-tau)^2-1).
// 2 columns per warp interleaved for ILP. Emits [hi || lo || hi] rows of g_A.
// ---------------------------------------------------------------------------
#define CPB 16

__global__ void entmax_kernel(const float* __restrict__ fa)
{
    __shared__ float s[256][CPB + 1];

    const int c0   = blockIdx.x * CPB;
    const int tid  = threadIdx.x;
    const int lane = tid & 31;
    const int w    = tid >> 5;

    #pragma unroll
    for (int i = 0; i < CPB; i++) {
        int e = tid + i * 256;
        int r = e >> 4;
        int c = e & 15;
        s[r][c] = 0.5f * fa[r * NCOLS + c0 + c];
    }
    __syncthreads();

    const int cA = 2 * w, cB = 2 * w + 1;

    float zA[8], zB[8];
    #pragma unroll
    for (int j = 0; j < 8; j++) {
        zA[j] = s[lane + 32 * j][cA];
        zB[j] = s[lane + 32 * j][cB];
    }

    float mA = zA[0], mB = zB[0];
    #pragma unroll
    for (int j = 1; j < 8; j++) { mA = fmaxf(mA, zA[j]); mB = fmaxf(mB, zB[j]); }
    #pragma unroll
    for (int off = 16; off > 0; off >>= 1) {
        mA = fmaxf(mA, __shfl_xor_sync(0xffffffffu, mA, off));
        mB = fmaxf(mB, __shfl_xor_sync(0xffffffffu, mB, off));
    }
    #pragma unroll
    for (int j = 0; j < 8; j++) { zA[j] -= mA; zB[j] -= mB; }

    float tauA = -1.0f, tauB = -1.0f;
    #pragma unroll 4
    for (int it = 0; it < 16; it++) {
        float s1A = 0.0f, s2A = 0.0f, s1B = 0.0f, s2B = 0.0f;
        #pragma unroll
        for (int j = 0; j < 8; j++) {
            float dA = fmaxf(zA[j] - tauA, 0.0f);
            float dB = fmaxf(zB[j] - tauB, 0.0f);
            s1A += dA; s2A = fmaf(dA, dA, s2A);
            s1B += dB; s2B = fmaf(dB, dB, s2B);
        }
        #pragma unroll
        for (int off = 16; off > 0; off >>= 1) {
            s1A += __shfl_xor_sync(0xffffffffu, s1A, off);
            s2A += __shfl_xor_sync(0xffffffffu, s2A, off);
            s1B += __shfl_xor_sync(0xffffffffu, s1B, off);
            s2B += __shfl_xor_sync(0xffffffffu, s2B, off);
        }
        tauA += (s2A - 1.0f) / (2.0f * s1A);
        tauB += (s2B - 1.0f) / (2.0f * s1B);
    }

    #pragma unroll
    for (int j = 0; j < 8; j++) {
        float dA = fmaxf(zA[j] - tauA, 0.0f);
        float dB = fmaxf(zB[j] - tauB, 0.0f);
        float wA = dA * dA, wB = dB * dB;
        __nv_bfloat16 hA = __float2bfloat16(wA);
        __nv_bfloat16 hB = __float2bfloat16(wB);
        int iA = (c0 + cA) * KP + lane + 32 * j;
        int iB = (c0 + cB) * KP + lane + 32 * j;
        g_A[iA]       = hA;
        g_A[iA + 256] = __float2bfloat16(wA - __bfloat162float(hA));
        g_A[iA + 512] = hA;
        g_A[iB]       = hB;
        g_A[iB + 256] = __float2bfloat16(wB - __bfloat162float(hB));
        g_A[iB + 512] = hB;
    }
}

// ---------------------------------------------------------------------------
// Kernel 2: HMMA bf16 GEMM  D[n,b] = sum_{k<768} A[n,k]*B[b,k]
//   = hiA.hiB + loA.hiB + hiA.loB  (drops only loA.loB ~ 2^-18)
// ---------------------------------------------------------------------------
#define CK 64
#define NKC (KP / CK)    // 12

#define SA0 0
#define SA1 16384
#define SB0 32768
#define SB1 40960
#define SM_TOTAL 49152

__device__ __forceinline__ void load_A_chunk(uint32_t sbase, int n0, int kc, int tid)
{
    #pragma unroll
    for (int j = 0; j < 4; j++) {
        int e = tid + j * 256;
        int row = e >> 3;
        int ch  = e & 7;
        cpa16(swz(sbase, row, ch * 16),
              g_A + (size_t)(n0 + row) * KP + kc * CK + ch * 8);
    }
}
__device__ __forceinline__ void load_B_chunk(uint32_t sbase, int b0, int kc, int tid)
{
    #pragma unroll
    for (int j = 0; j < 2; j++) {
        int e = tid + j * 256;
        int row = e >> 3;
        int ch  = e & 7;
        cpa16(swz(sbase, row, ch * 16),
              g_B + (size_t)(b0 + row) * KP + kc * CK + ch * 8);
    }
}

__global__ void __launch_bounds__(256, 1)
gemm_hmma_kernel(const float* __restrict__ thr,
                 const float* __restrict__ ltemp)
{
    extern __shared__ char smem[];
    const uint32_t sb = smem_u32(smem);
    const int tid  = threadIdx.x;
    const int lane = tid & 31;
    const int wid  = tid >> 5;
    const int wm   = wid >> 1;
    const int wn   = wid & 1;

    const int n0 = blockIdx.x * 128;
    const int b0 = blockIdx.y * 64;

    const uint32_t sA[2] = {sb + SA0, sb + SA1};
    const uint32_t sB[2] = {sb + SB0, sb + SB1};

    float acc[2][4][4];
    #pragma unroll
    for (int mi = 0; mi < 2; mi++)
        #pragma unroll
        for (int ni = 0; ni < 4; ni++)
            #pragma unroll
            for (int q = 0; q < 4; q++) acc[mi][ni][q] = 0.0f;

    load_A_chunk(sA[0], n0, 0, tid);
    load_B_chunk(sB[0], b0, 0, tid);
    asm volatile("cp.async.commit_group;");

    const int lane15 = lane & 15;
    const int khalf  = (lane >> 4) * 16;

    int buf = 0;
    for (int kc = 0; kc < NKC; kc++) {
        if (kc + 1 < NKC) {
            load_A_chunk(sA[buf ^ 1], n0, kc + 1, tid);
            load_B_chunk(sB[buf ^ 1], b0, kc + 1, tid);
            asm volatile("cp.async.commit_group;");
            asm volatile("cp.async.wait_group 1;");
        } else {
            asm volatile("cp.async.wait_group 0;");
        }
        __syncthreads();

        #pragma unroll
        for (int ks = 0; ks < 4; ks++) {
            const int kbyte = ks * 32 + khalf;
            uint32_t a0[4], a1[4], bq0[4], bq1[4];
            ldsm4(a0,  swz(sA[buf], wm * 32 + lane15,      kbyte));
            ldsm4(a1,  swz(sA[buf], wm * 32 + 16 + lane15, kbyte));
            ldsm4(bq0, swz(sB[buf], wn * 32 + lane15,      kbyte));
            ldsm4(bq1, swz(sB[buf], wn * 32 + 16 + lane15, kbyte));

            mma16816(acc[0][0], a0, bq0[0], bq0[2]);
            mma16816(acc[0][1], a0, bq0[1], bq0[3]);
            mma16816(acc[0][2], a0, bq1[0], bq1[2]);
            mma16816(acc[0][3], a0, bq1[1], bq1[3]);
            mma16816(acc[1][0], a1, bq0[0], bq0[2]);
            mma16816(acc[1][1], a1, bq0[1], bq0[3]);
            mma16816(acc[1][2], a1, bq1[0], bq1[2]);
            mma16816(acc[1][3], a1, bq1[1], bq1[3]);
        }
        __syncthreads();
        buf ^= 1;
    }

    const int qr = lane >> 2;
    const int qc = (lane & 3) * 2;
    #pragma unroll
    for (int mi = 0; mi < 2; mi++) {
        const int nr0 = n0 + wm * 32 + mi * 16 + qr;
        const int nr1 = nr0 + 8;
        const int t0 = nr0 / DEPTH, d0 = nr0 % DEPTH;
        const int t1 = nr1 / DEPTH, d1 = nr1 % DEPTH;
        const float th0 = thr[t0 * DEPTH + d0];
        const float sc0 = expf(-ltemp[t0 * DEPTH + d0]);
        const float th1 = thr[t1 * DEPTH + d1];
        const float sc1 = expf(-ltemp[t1 * DEPTH + d1]);
        #pragma unroll
        for (int ni = 0; ni < 4; ni++) {
            const int bc = b0 + wn * 32 + ni * 8 + qc;
            float2 v0, v1;
            v0.x = (acc[mi][ni][0] - th0) * sc0;
            v0.y = (acc[mi][ni][1] - th0) * sc0;
            v1.x = (acc[mi][ni][2] - th1) * sc1;
            v1.y = (acc[mi][ni][3] - th1) * sc1;
            *(float2*)&g_tl[(size_t)nr0 * BATCH + bc] = v0;
            *(float2*)&g_tl[(size_t)nr1 * BATCH + bc] = v1;
        }
    }
}

// ---------------------------------------------------------------------------
// Kernel 3 (v2): tile = 16 trees x 32 batches per block, 128 threads.
// - resp staged as float4 in smem (LDS.128 broadcast, 4x fewer shared issues)
// - leaves factored w8 (depths 0-2) x q8 (depths 3-5)
// - outputs staged in padded smem, then written as contiguous STG.128
// ---------------------------------------------------------------------------
#define TT 16   // trees per block
#define BB 32   // batches per block

__global__ void __launch_bounds__(128, 6)
leaf_kernel(const float* __restrict__ response,  // [512][3][64]
            float* __restrict__ out)             // [512][1536]
{
    __shared__ float4 rsp4[TT * 48];        // [tree][ch*16 + j*2 + half]
    __shared__ float  sout[BB][TT * 3 + 3]; // stride 51 (coprime to 32)

    const int t0   = blockIdx.x * TT;
    const int b0   = blockIdx.y * BB;
    const int tid  = threadIdx.x;
    const int lane = tid & 31;   // b_local
    const int tgrp = tid >> 5;   // 0..3, 4 trees each

    // Phase 1: stage response tile (TT*192 floats = TT*48 float4)
    {
        const float4* gr = (const float4*)response + (size_t)t0 * 48;
        #pragma unroll
        for (int i = 0; i < (TT * 48) / 128; i++)
            rsp4[tid + i * 128] = gr[tid + i * 128];
    }
    __syncthreads();

    const int b = b0 + lane;

    // Phase 2: each thread handles 4 trees for its batch
    #pragma unroll
    for (int tt = 0; tt < 4; tt++) {
        const int tl_ = tgrp * 4 + tt;        // tree local
        const int t   = t0 + tl_;

        float a[DEPTH], bb[DEPTH];
        #pragma unroll
        for (int d = 0; d < DEPTH; d++) {
            float v = g_tl[(size_t)(t * DEPTH + d) * BATCH + b];
            float x = 0.5f * v;
            a[d]  = fminf(fmaxf(0.5f + x, -0.5f), 1.5f);   // bit == 0
            bb[d] = fminf(fmaxf(0.5f - x, -0.5f), 1.5f);   // bit == 1
        }

        // w8 over depths 0..2 (leaf bits 0..2)
        float w8[8];
        w8[0] = 1.0f;
        #pragma unroll
        for (int d = 0; d < 3; d++) {
            const int sz = 1 << d;
            #pragma unroll
            for (int i = sz - 1; i >= 0; i--) {
                w8[i + sz] = w8[i] * bb[d];
                w8[i]      = w8[i] * a[d];
            }
        }
        // q8 over depths 3..5 (leaf bits 3..5)
        float q8[8];
        q8[0] = 1.0f;
        #pragma unroll
        for (int e = 0; e < 3; e++) {
            const int sz = 1 << e;
            #pragma unroll
            for (int i = sz - 1; i >= 0; i--) {
                q8[i + sz] = q8[i] * bb[3 + e];
                q8[i]      = q8[i] * a[3 + e];
            }
        }

        const float4* rp = &rsp4[tl_ * 48];
        float o0 = 0.0f, o1 = 0.0f, o2 = 0.0f;
        #pragma unroll
        for (int j = 0; j < 8; j++) {
            float4 r00 = rp[j * 2],      r01 = rp[j * 2 + 1];
            float4 r10 = rp[16 + j * 2], r11 = rp[16 + j * 2 + 1];
            float4 r20 = rp[32 + j * 2], r21 = rp[32 + j * 2 + 1];
            float s0 = w8[0]*r00.x + w8[1]*r00.y + w8[2]*r00.z + w8[3]*r00.w
                     + w8[4]*r01.x + w8[5]*r01.y + w8[6]*r01.z + w8[7]*r01.w;
            float s1 = w8[0]*r10.x + w8[1]*r10.y + w8[2]*r10.z + w8[3]*r10.w
                     + w8[4]*r11.x + w8[5]*r11.y + w8[6]*r11.z + w8[7]*r11.w;
            float s2 = w8[0]*r20.x + w8[1]*r20.y + w8[2]*r20.z + w8[3]*r20.w
                     + w8[4]*r21.x + w8[5]*r21.y + w8[6]*r21.z + w8[7]*r21.w;
            o0 = fmaf(q8[j], s0, o0);
            o1 = fmaf(q8[j], s1, o1);
            o2 = fmaf(q8[j], s2, o2);
        }

        sout[lane][tl_ * 3 + 0] = o0;
        sout[lane][tl_ * 3 + 1] = o1;
        sout[lane][tl_ * 3 + 2] = o2;
    }
    __syncthreads();

    // Phase 3: cooperative contiguous store. Block region: BB rows x 48 floats.
    #pragma unroll
    for (int i = 0; i < (BB * TT * 3) / (128 * 4); i++) {
        int fidx = tid + i * 128;            // float4 index, 12 per row
        int row  = fidx / 12;
        int col  = fidx % 12;
        float4 v;
        v.x = sout[row][col * 4 + 0];
        v.y = sout[row][col * 4 + 1];
        v.z = sout[row][col * 4 + 2];
        v.w = sout[row][col * 4 + 3];
        *(float4*)&out[(size_t)(b0 + row) * (NTREES * TDIM) + t0 * 3 + col * 4] = v;
    }
}

// ---------------------------------------------------------------------------
extern "C" void kernel_launch(void* const* d_in, const int* in_sizes, int n_in,
                              void* d_out, int out_size)
{
    const float* input    = (const float*)d_in[0];  // [512][256]
    const float* fa       = (const float*)d_in[1];  // [256][3072]
    const float* thr      = (const float*)d_in[2];  // [512][6]
    const float* ltemp    = (const float*)d_in[3];  // [512][6]
    const float* response = (const float*)d_in[4];  // [512][3][64]
    float* out = (float*)d_out;                     // [512][1536]

    cudaFuncSetAttribute(gemm_hmma_kernel,
                         cudaFuncAttributeMaxDynamicSharedMemorySize, SM_TOTAL);

    split_input_kernel<<<BATCH * F_IN / (4 * 256), 256>>>(input);
    entmax_kernel<<<NCOLS / CPB, 256>>>(fa);

    dim3 g2(NCOLS / 128, BATCH / 64);
    gemm_hmma_kernel<<<g2, 256, SM_TOTAL>>>(thr, ltemp);

    dim3 g3(NTREES / TT, BATCH / BB);
    leaf_kernel<<<g3, 128>>>(response, out);
}

// round 8
// speedup vs baseline: 2.8089x; 1.0701x over previous
#include <cuda_runtime.h>
#include <cuda_bf16.h>
#include <math.h>
#include <stdint.h>

// Problem constants
#define F_IN   256
#define NTREES 512
#define DEPTH  6
#define TDIM   3
#define BATCH  512
#define NCOLS  (NTREES * DEPTH)   // 3072
#define KP     768                // hi || lo || hi (A)  /  hi || hi || lo (B)

// Scratch (device globals)
__device__ __nv_bfloat16 g_A[NCOLS * KP];   // W^T: [n][k]=hi, [n][256+k]=lo, [n][512+k]=hi
__device__ __nv_bfloat16 g_B[BATCH * KP];   // in : [b][k]=hi, [b][256+k]=hi, [b][512+k]=lo
__device__ float g_tl[NCOLS * BATCH];       // thresholded logits [3072][512]

// ---------------------------------------------------------------------------
// Portable tensor-path helpers (sm_80+ baseline; ptxas targets plain sm_103)
// ---------------------------------------------------------------------------
__device__ __forceinline__ uint32_t smem_u32(const void* p) {
    uint32_t a;
    asm("{ .reg .u64 t; cvta.to.shared.u64 t, %1; cvt.u32.u64 %0, t; }" : "=r"(a) : "l"(p));
    return a;
}
__device__ __forceinline__ void cpa16(uint32_t dst, const void* src) {
    asm volatile("cp.async.cg.shared.global [%0], [%1], 16;" :: "r"(dst), "l"(src));
}
__device__ __forceinline__ void ldsm4(uint32_t* r, uint32_t addr) {
    asm volatile("ldmatrix.sync.aligned.m8n8.x4.shared.b16 {%0,%1,%2,%3}, [%4];"
                 : "=r"(r[0]), "=r"(r[1]), "=r"(r[2]), "=r"(r[3]) : "r"(addr));
}
__device__ __forceinline__ void mma16816(float* c, const uint32_t* a,
                                         uint32_t b0, uint32_t b1) {
    asm volatile(
        "mma.sync.aligned.m16n8k16.row.col.f32.bf16.bf16.f32 "
        "{%0,%1,%2,%3}, {%4,%5,%6,%7}, {%8,%9}, {%0,%1,%2,%3};"
        : "+f"(c[0]), "+f"(c[1]), "+f"(c[2]), "+f"(c[3])
        : "r"(a[0]), "r"(a[1]), "r"(a[2]), "r"(a[3]), "r"(b0), "r"(b1));
}
// 128B-row XOR swizzle: 16B chunk index ^= (row & 7)
__device__ __forceinline__ uint32_t swz(uint32_t base, int row, int kbyte) {
    uint32_t off = (uint32_t)(row * 128 + kbyte);
    return base + (off ^ ((off >> 3) & 0x70));
}

// ---------------------------------------------------------------------------
// Kernel 1 (fused): blocks [0,192) exact 1.5-entmax -> g_A [hi||lo||hi];
//                   blocks [192,320) split input    -> g_B [hi||hi||lo].
// entmax: Newton on g(tau)=sum relu(z-tau)^2-1 (convex => monotone),
// 2 columns per warp interleaved for ILP, 16 columns per block.
// ---------------------------------------------------------------------------
#define CPB 16
#define ENT_BLOCKS (NCOLS / CPB)          // 192
#define SPL_BLOCKS (BATCH * F_IN / 1024)  // 128

__global__ void prep_kernel(const float* __restrict__ fa,
                            const float* __restrict__ input)
{
    __shared__ float s[256][CPB + 1];

    const int tid  = threadIdx.x;

    if (blockIdx.x >= ENT_BLOCKS) {
        // ---- split input ----
        int i = (blockIdx.x - ENT_BLOCKS) * 256 + tid;  // float4 units
        int b = i >> 6;
        int r = i & 63;
        float4 v = ((const float4*)input)[i];
        float vals[4] = {v.x, v.y, v.z, v.w};
        __nv_bfloat16 hi[4], lo[4];
        #pragma unroll
        for (int j = 0; j < 4; j++) {
            hi[j] = __float2bfloat16(vals[j]);
            lo[j] = __float2bfloat16(vals[j] - __bfloat162float(hi[j]));
        }
        __nv_bfloat162 h0{hi[0], hi[1]}, h1{hi[2], hi[3]};
        __nv_bfloat162 l0{lo[0], lo[1]}, l1{lo[2], lo[3]};
        __nv_bfloat162* row = (__nv_bfloat162*)g_B + b * (KP / 2) + r * 2;
        row[0]   = h0;  row[1]   = h1;   // seg 0: hi
        row[128] = h0;  row[129] = h1;   // seg 1: hi
        row[256] = l0;  row[257] = l1;   // seg 2: lo
        return;
    }

    // ---- entmax ----
    const int c0   = blockIdx.x * CPB;
    const int lane = tid & 31;
    const int w    = tid >> 5;

    #pragma unroll
    for (int i = 0; i < CPB; i++) {
        int e = tid + i * 256;
        int r = e >> 4;
        int c = e & 15;
        s[r][c] = 0.5f * fa[r * NCOLS + c0 + c];
    }
    __syncthreads();

    const int cA = 2 * w, cB = 2 * w + 1;

    float zA[8], zB[8];
    #pragma unroll
    for (int j = 0; j < 8; j++) {
        zA[j] = s[lane + 32 * j][cA];
        zB[j] = s[lane + 32 * j][cB];
    }

    float mA = zA[0], mB = zB[0];
    #pragma unroll
    for (int j = 1; j < 8; j++) { mA = fmaxf(mA, zA[j]); mB = fmaxf(mB, zB[j]); }
    #pragma unroll
    for (int off = 16; off > 0; off >>= 1) {
        mA = fmaxf(mA, __shfl_xor_sync(0xffffffffu, mA, off));
        mB = fmaxf(mB, __shfl_xor_sync(0xffffffffu, mB, off));
    }
    #pragma unroll
    for (int j = 0; j < 8; j++) { zA[j] -= mA; zB[j] -= mB; }

    float tauA = -1.0f, tauB = -1.0f;
    #pragma unroll 4
    for (int it = 0; it < 16; it++) {
        float s1A = 0.0f, s2A = 0.0f, s1B = 0.0f, s2B = 0.0f;
        #pragma unroll
        for (int j = 0; j < 8; j++) {
            float dA = fmaxf(zA[j] - tauA, 0.0f);
            float dB = fmaxf(zB[j] - tauB, 0.0f);
            s1A += dA; s2A = fmaf(dA, dA, s2A);
            s1B += dB; s2B = fmaf(dB, dB, s2B);
        }
        #pragma unroll
        for (int off = 16; off > 0; off >>= 1) {
            s1A += __shfl_xor_sync(0xffffffffu, s1A, off);
            s2A += __shfl_xor_sync(0xffffffffu, s2A, off);
            s1B += __shfl_xor_sync(0xffffffffu, s1B, off);
            s2B += __shfl_xor_sync(0xffffffffu, s2B, off);
        }
        tauA += (s2A - 1.0f) / (2.0f * s1A);
        tauB += (s2B - 1.0f) / (2.0f * s1B);
    }

    #pragma unroll
    for (int j = 0; j < 8; j++) {
        float dA = fmaxf(zA[j] - tauA, 0.0f);
        float dB = fmaxf(zB[j] - tauB, 0.0f);
        float wA = dA * dA, wB = dB * dB;
        __nv_bfloat16 hA = __float2bfloat16(wA);
        __nv_bfloat16 hB = __float2bfloat16(wB);
        int iA = (c0 + cA) * KP + lane + 32 * j;
        int iB = (c0 + cB) * KP + lane + 32 * j;
        g_A[iA]       = hA;
        g_A[iA + 256] = __float2bfloat16(wA - __bfloat162float(hA));
        g_A[iA + 512] = hA;
        g_A[iB]       = hB;
        g_A[iB + 256] = __float2bfloat16(wB - __bfloat162float(hB));
        g_A[iB + 512] = hB;
    }
}

// ---------------------------------------------------------------------------
// Kernel 2: HMMA bf16 GEMM  D[n,b] = sum_{k<768} A[n,k]*B[b,k]
//   = hiA.hiB + loA.hiB + hiA.loB  (drops only loA.loB ~ 2^-18)
// CTA: M=128(n) x N=64(b), 8 warps of 32x32, K chunks of 64, double-buffered
// cp.async, XOR-swizzled smem, ldmatrix.x4, fused threshold epilogue.
// ---------------------------------------------------------------------------
#define CK 64
#define NKC (KP / CK)    // 12

#define SA0 0
#define SA1 16384
#define SB0 32768
#define SB1 40960
#define SM_TOTAL 49152

__device__ __forceinline__ void load_A_chunk(uint32_t sbase, int n0, int kc, int tid)
{
    #pragma unroll
    for (int j = 0; j < 4; j++) {
        int e = tid + j * 256;
        int row = e >> 3;
        int ch  = e & 7;
        cpa16(swz(sbase, row, ch * 16),
              g_A + (size_t)(n0 + row) * KP + kc * CK + ch * 8);
    }
}
__device__ __forceinline__ void load_B_chunk(uint32_t sbase, int b0, int kc, int tid)
{
    #pragma unroll
    for (int j = 0; j < 2; j++) {
        int e = tid + j * 256;
        int row = e >> 3;
        int ch  = e & 7;
        cpa16(swz(sbase, row, ch * 16),
              g_B + (size_t)(b0 + row) * KP + kc * CK + ch * 8);
    }
}

__global__ void __launch_bounds__(256, 2)
gemm_hmma_kernel(const float* __restrict__ thr,
                 const float* __restrict__ ltemp)
{
    extern __shared__ char smem[];
    const uint32_t sb = smem_u32(smem);
    const int tid  = threadIdx.x;
    const int lane = tid & 31;
    const int wid  = tid >> 5;
    const int wm   = wid >> 1;
    const int wn   = wid & 1;

    const int n0 = blockIdx.x * 128;
    const int b0 = blockIdx.y * 64;

    const uint32_t sA[2] = {sb + SA0, sb + SA1};
    const uint32_t sB[2] = {sb + SB0, sb + SB1};

    float acc[2][4][4];
    #pragma unroll
    for (int mi = 0; mi < 2; mi++)
        #pragma unroll
        for (int ni = 0; ni < 4; ni++)
            #pragma unroll
            for (int q = 0; q < 4; q++) acc[mi][ni][q] = 0.0f;

    load_A_chunk(sA[0], n0, 0, tid);
    load_B_chunk(sB[0], b0, 0, tid);
    asm volatile("cp.async.commit_group;");

    const int lane15 = lane & 15;
    const int khalf  = (lane >> 4) * 16;

    int buf = 0;
    for (int kc = 0; kc < NKC; kc++) {
        if (kc + 1 < NKC) {
            load_A_chunk(sA[buf ^ 1], n0, kc + 1, tid);
            load_B_chunk(sB[buf ^ 1], b0, kc + 1, tid);
            asm volatile("cp.async.commit_group;");
            asm volatile("cp.async.wait_group 1;");
        } else {
            asm volatile("cp.async.wait_group 0;");
        }
        __syncthreads();

        #pragma unroll
        for (int ks = 0; ks < 4; ks++) {
            const int kbyte = ks * 32 + khalf;
            uint32_t a0[4], a1[4], bq0[4], bq1[4];
            ldsm4(a0,  swz(sA[buf], wm * 32 + lane15,      kbyte));
            ldsm4(a1,  swz(sA[buf], wm * 32 + 16 + lane15, kbyte));
            ldsm4(bq0, swz(sB[buf], wn * 32 + lane15,      kbyte));
            ldsm4(bq1, swz(sB[buf], wn * 32 + 16 + lane15, kbyte));

            mma16816(acc[0][0], a0, bq0[0], bq0[2]);
            mma16816(acc[0][1], a0, bq0[1], bq0[3]);
            mma16816(acc[0][2], a0, bq1[0], bq1[2]);
            mma16816(acc[0][3], a0, bq1[1], bq1[3]);
            mma16816(acc[1][0], a1, bq0[0], bq0[2]);
            mma16816(acc[1][1], a1, bq0[1], bq0[3]);
            mma16816(acc[1][2], a1, bq1[0], bq1[2]);
            mma16816(acc[1][3], a1, bq1[1], bq1[3]);
        }
        __syncthreads();
        buf ^= 1;
    }

    const int qr = lane >> 2;
    const int qc = (lane & 3) * 2;
    #pragma unroll
    for (int mi = 0; mi < 2; mi++) {
        const int nr0 = n0 + wm * 32 + mi * 16 + qr;
        const int nr1 = nr0 + 8;
        const int t0 = nr0 / DEPTH, d0 = nr0 % DEPTH;
        const int t1 = nr1 / DEPTH, d1 = nr1 % DEPTH;
        const float th0 = thr[t0 * DEPTH + d0];
        const float sc0 = expf(-ltemp[t0 * DEPTH + d0]);
        const float th1 = thr[t1 * DEPTH + d1];
        const float sc1 = expf(-ltemp[t1 * DEPTH + d1]);
        #pragma unroll
        for (int ni = 0; ni < 4; ni++) {
            const int bc = b0 + wn * 32 + ni * 8 + qc;
            float2 v0, v1;
            v0.x = (acc[mi][ni][0] - th0) * sc0;
            v0.y = (acc[mi][ni][1] - th0) * sc0;
            v1.x = (acc[mi][ni][2] - th1) * sc1;
            v1.y = (acc[mi][ni][3] - th1) * sc1;
            *(float2*)&g_tl[(size_t)nr0 * BATCH + bc] = v0;
            *(float2*)&g_tl[(size_t)nr1 * BATCH + bc] = v1;
        }
    }
}

// ---------------------------------------------------------------------------
// Kernel 3 (v3): one (tree, batch) pair per thread.
// Block = 256 threads = 8 warps; warp w handles tree t0+w, lanes = 32 batches.
// tl loads coalesced; resp reads are warp-uniform LDS.128 broadcasts.
// Outputs staged in padded smem, then contiguous cooperative STG.128.
// ---------------------------------------------------------------------------
#define TT 8    // trees per block
#define BB 32   // batches per block

__global__ void __launch_bounds__(256, 4)
leaf_kernel(const float* __restrict__ response,  // [512][3][64]
            float* __restrict__ out)             // [512][1536]
{
    __shared__ float4 rsp4[TT * 48];         // [tree][ch*16 + j*2 + half]
    __shared__ float  sout[BB][TT * 3 + 3];  // stride 27, coprime to 32

    const int t0   = blockIdx.x * TT;
    const int b0   = blockIdx.y * BB;
    const int tid  = threadIdx.x;
    const int lane = tid & 31;   // batch within block
    const int w    = tid >> 5;   // tree within block

    // stage response tile: TT*48 float4 = 384
    for (int i = tid; i < TT * 48; i += 256)
        rsp4[i] = ((const float4*)response)[(size_t)t0 * 48 + i];
    __syncthreads();

    const int t = t0 + w;
    const int b = b0 + lane;

    float a[DEPTH], bb[DEPTH];
    #pragma unroll
    for (int d = 0; d < DEPTH; d++) {
        float v = g_tl[(size_t)(t * DEPTH + d) * BATCH + b];
        float x = 0.5f * v;
        a[d]  = fminf(fmaxf(0.5f + x, -0.5f), 1.5f);   // bit == 0
        bb[d] = fminf(fmaxf(0.5f - x, -0.5f), 1.5f);   // bit == 1
    }

    // w8 over depths 0..2 (leaf bits 0..2)
    float w8[8];
    w8[0] = 1.0f;
    #pragma unroll
    for (int d = 0; d < 3; d++) {
        const int sz = 1 << d;
        #pragma unroll
        for (int i = sz - 1; i >= 0; i--) {
            w8[i + sz] = w8[i] * bb[d];
            w8[i]      = w8[i] * a[d];
        }
    }
    // q8 over depths 3..5 (leaf bits 3..5)
    float q8[8];
    q8[0] = 1.0f;
    #pragma unroll
    for (int e = 0; e < 3; e++) {
        const int sz = 1 << e;
        #pragma unroll
        for (int i = sz - 1; i >= 0; i--) {
            q8[i + sz] = q8[i] * bb[3 + e];
            q8[i]      = q8[i] * a[3 + e];
        }
    }

    const float4* rp = &rsp4[w * 48];
    float o0 = 0.0f, o1 = 0.0f, o2 = 0.0f;
    #pragma unroll
    for (int j = 0; j < 8; j++) {
        float4 r00 = rp[j * 2],      r01 = rp[j * 2 + 1];
        float4 r10 = rp[16 + j * 2], r11 = rp[16 + j * 2 + 1];
        float4 r20 = rp[32 + j * 2], r21 = rp[32 + j * 2 + 1];
        float s0 = w8[0]*r00.x + w8[1]*r00.y + w8[2]*r00.z + w8[3]*r00.w
                 + w8[4]*r01.x + w8[5]*r01.y + w8[6]*r01.z + w8[7]*r01.w;
        float s1 = w8[0]*r10.x + w8[1]*r10.y + w8[2]*r10.z + w8[3]*r10.w
                 + w8[4]*r11.x + w8[5]*r11.y + w8[6]*r11.z + w8[7]*r11.w;
        float s2 = w8[0]*r20.x + w8[1]*r20.y + w8[2]*r20.z + w8[3]*r20.w
                 + w8[4]*r21.x + w8[5]*r21.y + w8[6]*r21.z + w8[7]*r21.w;
        o0 = fmaf(q8[j], s0, o0);
        o1 = fmaf(q8[j], s1, o1);
        o2 = fmaf(q8[j], s2, o2);
    }

    sout[lane][w * 3 + 0] = o0;
    sout[lane][w * 3 + 1] = o1;
    sout[lane][w * 3 + 2] = o2;
    __syncthreads();

    // cooperative contiguous store: BB rows x TT*3 floats = 192 float4
    {
        int fidx = tid;                      // 192 < 256: one per thread
        if (fidx < (BB * TT * 3) / 4) {
            int row = fidx / 6;              // 6 float4 per row
            int col = fidx % 6;
            float4 v;
            v.x = sout[row][col * 4 + 0];
            v.y = sout[row][col * 4 + 1];
            v.z = sout[row][col * 4 + 2];
            v.w = sout[row][col * 4 + 3];
            *(float4*)&out[(size_t)(b0 + row) * (NTREES * TDIM) + t0 * 3 + col * 4] = v;
        }
    }
}

// ---------------------------------------------------------------------------
extern "C" void kernel_launch(void* const* d_in, const int* in_sizes, int n_in,
                              void* d_out, int out_size)
{
    const float* input    = (const float*)d_in[0];  // [512][256]
    const float* fa       = (const float*)d_in[1];  // [256][3072]
    const float* thr      = (const float*)d_in[2];  // [512][6]
    const float* ltemp    = (const float*)d_in[3];  // [512][6]
    const float* response = (const float*)d_in[4];  // [512][3][64]
    float* out = (float*)d_out;                     // [512][1536]

    cudaFuncSetAttribute(gemm_hmma_kernel,
                         cudaFuncAttributeMaxDynamicSharedMemorySize, SM_TOTAL);

    prep_kernel<<<ENT_BLOCKS + SPL_BLOCKS, 256>>>(fa, input);

    dim3 g2(NCOLS / 128, BATCH / 64);
    gemm_hmma_kernel<<<g2, 256, SM_TOTAL>>>(thr, ltemp);

    dim3 g3(NTREES / TT, BATCH / BB);
    leaf_kernel<<<g3, 256>>>(response, out);
}

// round 9
// speedup vs baseline: 3.1662x; 1.1272x over previous
#include <cuda_runtime.h>
#include <cuda_bf16.h>
#include <math.h>
#include <stdint.h>

// Problem constants
#define F_IN   256
#define NTREES 512
#define DEPTH  6
#define TDIM   3
#define BATCH  512
#define NCOLS  (NTREES * DEPTH)   // 3072
#define KP     768                // hi || lo || hi (A)  /  hi || hi || lo (B)

// Scratch (device globals)
__device__ __nv_bfloat16 g_A[NCOLS * KP];   // W^T: [n][k]=hi, [n][256+k]=lo, [n][512+k]=hi
__device__ __nv_bfloat16 g_B[BATCH * KP];   // in : [b][k]=hi, [b][256+k]=hi, [b][512+k]=lo
__device__ float g_tl[NCOLS * BATCH];       // thresholded logits [3072][512]

// ---------------------------------------------------------------------------
// Portable tensor-path helpers (sm_80+ baseline; ptxas targets plain sm_103)
// ---------------------------------------------------------------------------
__device__ __forceinline__ uint32_t smem_u32(const void* p) {
    uint32_t a;
    asm("{ .reg .u64 t; cvta.to.shared.u64 t, %1; cvt.u32.u64 %0, t; }" : "=r"(a) : "l"(p));
    return a;
}
__device__ __forceinline__ void cpa16(uint32_t dst, const void* src) {
    asm volatile("cp.async.cg.shared.global [%0], [%1], 16;" :: "r"(dst), "l"(src));
}
__device__ __forceinline__ void ldsm4(uint32_t* r, uint32_t addr) {
    asm volatile("ldmatrix.sync.aligned.m8n8.x4.shared.b16 {%0,%1,%2,%3}, [%4];"
                 : "=r"(r[0]), "=r"(r[1]), "=r"(r[2]), "=r"(r[3]) : "r"(addr));
}
__device__ __forceinline__ void mma16816(float* c, const uint32_t* a,
                                         uint32_t b0, uint32_t b1) {
    asm volatile(
        "mma.sync.aligned.m16n8k16.row.col.f32.bf16.bf16.f32 "
        "{%0,%1,%2,%3}, {%4,%5,%6,%7}, {%8,%9}, {%0,%1,%2,%3};"
        : "+f"(c[0]), "+f"(c[1]), "+f"(c[2]), "+f"(c[3])
        : "r"(a[0]), "r"(a[1]), "r"(a[2]), "r"(a[3]), "r"(b0), "r"(b1));
}
// 128B-row XOR swizzle: 16B chunk index ^= (row & 7)
__device__ __forceinline__ uint32_t swz(uint32_t base, int row, int kbyte) {
    uint32_t off = (uint32_t)(row * 128 + kbyte);
    return base + (off ^ ((off >> 3) & 0x70));
}

// ---------------------------------------------------------------------------
// Kernel 1a: exact 1.5-entmax -> g_A [hi||lo||hi].
// Newton on g(tau)=sum relu(z-tau)^2-1 (convex => monotone from tau0).
// 4 columns per warp, 8 interleaved reduction chains for ILP.
// Block = 128 threads = 4 warps = 16 columns. Fast division (MUFU.RCP).
// ---------------------------------------------------------------------------
#define CPB 16
#define ENT_BLOCKS (NCOLS / CPB)          // 192
#define SPL_BLOCKS (BATCH * F_IN / 512)   // 256 (128 thr x float4)

__global__ void __launch_bounds__(128, 8)
prep_kernel(const float* __restrict__ fa,
            const float* __restrict__ input)
{
    const int tid = threadIdx.x;

    if (blockIdx.x >= ENT_BLOCKS) {
        // ---- split input: [hi || hi || lo] rows of g_B ----
        int i = (blockIdx.x - ENT_BLOCKS) * 128 + tid;  // float4 units
        int b = i >> 6;
        int r = i & 63;
        float4 v = ((const float4*)input)[i];
        float vals[4] = {v.x, v.y, v.z, v.w};
        __nv_bfloat16 hi[4], lo[4];
        #pragma unroll
        for (int j = 0; j < 4; j++) {
            hi[j] = __float2bfloat16(vals[j]);
            lo[j] = __float2bfloat16(vals[j] - __bfloat162float(hi[j]));
        }
        __nv_bfloat162 h0{hi[0], hi[1]}, h1{hi[2], hi[3]};
        __nv_bfloat162 l0{lo[0], lo[1]}, l1{lo[2], lo[3]};
        __nv_bfloat162* row = (__nv_bfloat162*)g_B + b * (KP / 2) + r * 2;
        row[0]   = h0;  row[1]   = h1;   // seg 0: hi
        row[128] = h0;  row[129] = h1;   // seg 1: hi
        row[256] = l0;  row[257] = l1;   // seg 2: lo
        return;
    }

    // ---- entmax ----
    __shared__ float s[256][CPB + 1];

    const int c0   = blockIdx.x * CPB;
    const int lane = tid & 31;
    const int w    = tid >> 5;

    #pragma unroll
    for (int i = 0; i < 32; i++) {
        int e = tid + i * 128;
        int r = e >> 4;
        int c = e & 15;
        s[r][c] = 0.5f * fa[r * NCOLS + c0 + c];
    }
    __syncthreads();

    const int cc = 4 * w;   // this warp's 4 columns: cc..cc+3

    float z[4][8];
    #pragma unroll
    for (int q = 0; q < 4; q++)
        #pragma unroll
        for (int j = 0; j < 8; j++)
            z[q][j] = s[lane + 32 * j][cc + q];

    // per-column max (4 interleaved butterflies)
    float m[4];
    #pragma unroll
    for (int q = 0; q < 4; q++) {
        m[q] = z[q][0];
        #pragma unroll
        for (int j = 1; j < 8; j++) m[q] = fmaxf(m[q], z[q][j]);
    }
    #pragma unroll
    for (int off = 16; off > 0; off >>= 1) {
        #pragma unroll
        for (int q = 0; q < 4; q++)
            m[q] = fmaxf(m[q], __shfl_xor_sync(0xffffffffu, m[q], off));
    }
    #pragma unroll
    for (int q = 0; q < 4; q++)
        #pragma unroll
        for (int j = 0; j < 8; j++)
            z[q][j] -= m[q];

    // Newton: tau0 = -1 (max(z)=0); monotone from below; fast division.
    float tau[4] = {-1.0f, -1.0f, -1.0f, -1.0f};
    for (int it = 0; it < 14; it++) {
        float s1[4], s2[4];
        #pragma unroll
        for (int q = 0; q < 4; q++) {
            s1[q] = 0.0f; s2[q] = 0.0f;
            #pragma unroll
            for (int j = 0; j < 8; j++) {
                float d = fmaxf(z[q][j] - tau[q], 0.0f);
                s1[q] += d;
                s2[q] = fmaf(d, d, s2[q]);
            }
        }
        #pragma unroll
        for (int off = 16; off > 0; off >>= 1) {
            #pragma unroll
            for (int q = 0; q < 4; q++) {
                s1[q] += __shfl_xor_sync(0xffffffffu, s1[q], off);
                s2[q] += __shfl_xor_sync(0xffffffffu, s2[q], off);
            }
        }
        #pragma unroll
        for (int q = 0; q < 4; q++)
            tau[q] += __fdividef(s2[q] - 1.0f, 2.0f * s1[q]);
    }

    // emit [hi || lo || hi] rows of g_A
    #pragma unroll
    for (int q = 0; q < 4; q++) {
        #pragma unroll
        for (int j = 0; j < 8; j++) {
            float d = fmaxf(z[q][j] - tau[q], 0.0f);
            float wv = d * d;
            __nv_bfloat16 h = __float2bfloat16(wv);
            int idx = (c0 + cc + q) * KP + lane + 32 * j;
            g_A[idx]       = h;
            g_A[idx + 256] = __float2bfloat16(wv - __bfloat162float(h));
            g_A[idx + 512] = h;
        }
    }
}

// ---------------------------------------------------------------------------
// Kernel 2: HMMA bf16 GEMM  D[n,b] = sum_{k<768} A[n,k]*B[b,k]
//   = hiA.hiB + loA.hiB + hiA.loB  (drops only loA.loB ~ 2^-18)
// CTA: M=128(n) x N=64(b), 8 warps of 32x32, K chunks of 64, double-buffered
// cp.async, XOR-swizzled smem, ldmatrix.x4, fused threshold epilogue.
// ---------------------------------------------------------------------------
#define CK 64
#define NKC (KP / CK)    // 12

#define SA0 0
#define SA1 16384
#define SB0 32768
#define SB1 40960
#define SM_TOTAL 49152

__device__ __forceinline__ void load_A_chunk(uint32_t sbase, int n0, int kc, int tid)
{
    #pragma unroll
    for (int j = 0; j < 4; j++) {
        int e = tid + j * 256;
        int row = e >> 3;
        int ch  = e & 7;
        cpa16(swz(sbase, row, ch * 16),
              g_A + (size_t)(n0 + row) * KP + kc * CK + ch * 8);
    }
}
__device__ __forceinline__ void load_B_chunk(uint32_t sbase, int b0, int kc, int tid)
{
    #pragma unroll
    for (int j = 0; j < 2; j++) {
        int e = tid + j * 256;
        int row = e >> 3;
        int ch  = e & 7;
        cpa16(swz(sbase, row, ch * 16),
              g_B + (size_t)(b0 + row) * KP + kc * CK + ch * 8);
    }
}

__global__ void __launch_bounds__(256, 2)
gemm_hmma_kernel(const float* __restrict__ thr,
                 const float* __restrict__ ltemp)
{
    extern __shared__ char smem[];
    const uint32_t sb = smem_u32(smem);
    const int tid  = threadIdx.x;
    const int lane = tid & 31;
    const int wid  = tid >> 5;
    const int wm   = wid >> 1;
    const int wn   = wid & 1;

    const int n0 = blockIdx.x * 128;
    const int b0 = blockIdx.y * 64;

    const uint32_t sA[2] = {sb + SA0, sb + SA1};
    const uint32_t sB[2] = {sb + SB0, sb + SB1};

    float acc[2][4][4];
    #pragma unroll
    for (int mi = 0; mi < 2; mi++)
        #pragma unroll
        for (int ni = 0; ni < 4; ni++)
            #pragma unroll
            for (int q = 0; q < 4; q++) acc[mi][ni][q] = 0.0f;

    load_A_chunk(sA[0], n0, 0, tid);
    load_B_chunk(sB[0], b0, 0, tid);
    asm volatile("cp.async.commit_group;");

    const int lane15 = lane & 15;
    const int khalf  = (lane >> 4) * 16;

    int buf = 0;
    for (int kc = 0; kc < NKC; kc++) {
        if (kc + 1 < NKC) {
            load_A_chunk(sA[buf ^ 1], n0, kc + 1, tid);
            load_B_chunk(sB[buf ^ 1], b0, kc + 1, tid);
            asm volatile("cp.async.commit_group;");
            asm volatile("cp.async.wait_group 1;");
        } else {
            asm volatile("cp.async.wait_group 0;");
        }
        __syncthreads();

        #pragma unroll
        for (int ks = 0; ks < 4; ks++) {
            const int kbyte = ks * 32 + khalf;
            uint32_t a0[4], a1[4], bq0[4], bq1[4];
            ldsm4(a0,  swz(sA[buf], wm * 32 + lane15,      kbyte));
            ldsm4(a1,  swz(sA[buf], wm * 32 + 16 + lane15, kbyte));
            ldsm4(bq0, swz(sB[buf], wn * 32 + lane15,      kbyte));
            ldsm4(bq1, swz(sB[buf], wn * 32 + 16 + lane15, kbyte));

            mma16816(acc[0][0], a0, bq0[0], bq0[2]);
            mma16816(acc[0][1], a0, bq0[1], bq0[3]);
            mma16816(acc[0][2], a0, bq1[0], bq1[2]);
            mma16816(acc[0][3], a0, bq1[1], bq1[3]);
            mma16816(acc[1][0], a1, bq0[0], bq0[2]);
            mma16816(acc[1][1], a1, bq0[1], bq0[3]);
            mma16816(acc[1][2], a1, bq1[0], bq1[2]);
            mma16816(acc[1][3], a1, bq1[1], bq1[3]);
        }
        __syncthreads();
        buf ^= 1;
    }

    const int qr = lane >> 2;
    const int qc = (lane & 3) * 2;
    #pragma unroll
    for (int mi = 0; mi < 2; mi++) {
        const int nr0 = n0 + wm * 32 + mi * 16 + qr;
        const int nr1 = nr0 + 8;
        const int t0 = nr0 / DEPTH, d0 = nr0 % DEPTH;
        const int t1 = nr1 / DEPTH, d1 = nr1 % DEPTH;
        const float th0 = thr[t0 * DEPTH + d0];
        const float sc0 = expf(-ltemp[t0 * DEPTH + d0]);
        const float th1 = thr[t1 * DEPTH + d1];
        const float sc1 = expf(-ltemp[t1 * DEPTH + d1]);
        #pragma unroll
        for (int ni = 0; ni < 4; ni++) {
            const int bc = b0 + wn * 32 + ni * 8 + qc;
            float2 v0, v1;
            v0.x = (acc[mi][ni][0] - th0) * sc0;
            v0.y = (acc[mi][ni][1] - th0) * sc0;
            v1.x = (acc[mi][ni][2] - th1) * sc1;
            v1.y = (acc[mi][ni][3] - th1) * sc1;
            *(float2*)&g_tl[(size_t)nr0 * BATCH + bc] = v0;
            *(float2*)&g_tl[(size_t)nr1 * BATCH + bc] = v1;
        }
    }
}

// ---------------------------------------------------------------------------
// Kernel 3: one (tree, batch) pair per thread. Block = 8 trees x 32 batches.
// ---------------------------------------------------------------------------
#define TT 8    // trees per block
#define BB 32   // batches per block

__global__ void __launch_bounds__(256, 4)
leaf_kernel(const float* __restrict__ response,  // [512][3][64]
            float* __restrict__ out)             // [512][1536]
{
    __shared__ float4 rsp4[TT * 48];
    __shared__ float  sout[BB][TT * 3 + 3];

    const int t0   = blockIdx.x * TT;
    const int b0   = blockIdx.y * BB;
    const int tid  = threadIdx.x;
    const int lane = tid & 31;
    const int w    = tid >> 5;

    for (int i = tid; i < TT * 48; i += 256)
        rsp4[i] = ((const float4*)response)[(size_t)t0 * 48 + i];
    __syncthreads();

    const int t = t0 + w;
    const int b = b0 + lane;

    float a[DEPTH], bb[DEPTH];
    #pragma unroll
    for (int d = 0; d < DEPTH; d++) {
        float v = g_tl[(size_t)(t * DEPTH + d) * BATCH + b];
        float x = 0.5f * v;
        a[d]  = fminf(fmaxf(0.5f + x, -0.5f), 1.5f);
        bb[d] = fminf(fmaxf(0.5f - x, -0.5f), 1.5f);
    }

    float w8[8];
    w8[0] = 1.0f;
    #pragma unroll
    for (int d = 0; d < 3; d++) {
        const int sz = 1 << d;
        #pragma unroll
        for (int i = sz - 1; i >= 0; i--) {
            w8[i + sz] = w8[i] * bb[d];
            w8[i]      = w8[i] * a[d];
        }
    }
    float q8[8];
    q8[0] = 1.0f;
    #pragma unroll
    for (int e = 0; e < 3; e++) {
        const int sz = 1 << e;
        #pragma unroll
        for (int i = sz - 1; i >= 0; i--) {
            q8[i + sz] = q8[i] * bb[3 + e];
            q8[i]      = q8[i] * a[3 + e];
        }
    }

    const float4* rp = &rsp4[w * 48];
    float o0 = 0.0f, o1 = 0.0f, o2 = 0.0f;
    #pragma unroll
    for (int j = 0; j < 8; j++) {
        float4 r00 = rp[j * 2],      r01 = rp[j * 2 + 1];
        float4 r10 = rp[16 + j * 2], r11 = rp[16 + j * 2 + 1];
        float4 r20 = rp[32 + j * 2], r21 = rp[32 + j * 2 + 1];
        float s0 = w8[0]*r00.x + w8[1]*r00.y + w8[2]*r00.z + w8[3]*r00.w
                 + w8[4]*r01.x + w8[5]*r01.y + w8[6]*r01.z + w8[7]*r01.w;
        float s1 = w8[0]*r10.x + w8[1]*r10.y + w8[2]*r10.z + w8[3]*r10.w
                 + w8[4]*r11.x + w8[5]*r11.y + w8[6]*r11.z + w8[7]*r11.w;
        float s2 = w8[0]*r20.x + w8[1]*r20.y + w8[2]*r20.z + w8[3]*r20.w
                 + w8[4]*r21.x + w8[5]*r21.y + w8[6]*r21.z + w8[7]*r21.w;
        o0 = fmaf(q8[j], s0, o0);
        o1 = fmaf(q8[j], s1, o1);
        o2 = fmaf(q8[j], s2, o2);
    }

    sout[lane][w * 3 + 0] = o0;
    sout[lane][w * 3 + 1] = o1;
    sout[lane][w * 3 + 2] = o2;
    __syncthreads();

    if (tid < (BB * TT * 3) / 4) {
        int row = tid / 6;
        int col = tid % 6;
        float4 v;
        v.x = sout[row][col * 4 + 0];
        v.y = sout[row][col * 4 + 1];
        v.z = sout[row][col * 4 + 2];
        v.w = sout[row][col * 4 + 3];
        *(float4*)&out[(size_t)(b0 + row) * (NTREES * TDIM) + t0 * 3 + col * 4] = v;
    }
}

// ---------------------------------------------------------------------------
extern "C" void kernel_launch(void* const* d_in, const int* in_sizes, int n_in,
                              void* d_out, int out_size)
{
    const float* input    = (const float*)d_in[0];  // [512][256]
    const float* fa       = (const float*)d_in[1];  // [256][3072]
    const float* thr      = (const float*)d_in[2];  // [512][6]
    const float* ltemp    = (const float*)d_in[3];  // [512][6]
    const float* response = (const float*)d_in[4];  // [512][3][64]
    float* out = (float*)d_out;                     // [512][1536]

    cudaFuncSetAttribute(gemm_hmma_kernel,
                         cudaFuncAttributeMaxDynamicSharedMemorySize, SM_TOTAL);

    prep_kernel<<<ENT_BLOCKS + SPL_BLOCKS, 128>>>(fa, input);

    dim3 g2(NCOLS / 128, BATCH / 64);
    gemm_hmma_kernel<<<g2, 256, SM_TOTAL>>>(thr, ltemp);

    dim3 g3(NTREES / TT, BATCH / BB);
    leaf_kernel<<<g3, 256>>>(response, out);
}

// round 10
// speedup vs baseline: 3.3701x; 1.0644x over previous
#include <cuda_runtime.h>
#include <cuda_bf16.h>
#include <math.h>
#include <stdint.h>

// Problem constants
#define F_IN   256
#define NTREES 512
#define DEPTH  6
#define TDIM   3
#define BATCH  512
#define NCOLS  (NTREES * DEPTH)   // 3072
#define KS     512                // stored K: [hi || lo]
#define KV     768                // virtual K in GEMM: hi.hi + lo.hi + hi.lo

// Scratch (device globals)
__device__ __nv_bfloat16 g_A[NCOLS * KS];   // W^T: [n][k]=hi, [n][256+k]=lo
__device__ __nv_bfloat16 g_B[BATCH * KS];   // in : [b][k]=hi, [b][256+k]=lo
__device__ float g_tl[NCOLS * BATCH];       // thresholded logits [3072][512]

// ---------------------------------------------------------------------------
// Portable tensor-path helpers (sm_80+ baseline; ptxas targets plain sm_103)
// ---------------------------------------------------------------------------
__device__ __forceinline__ uint32_t smem_u32(const void* p) {
    uint32_t a;
    asm("{ .reg .u64 t; cvta.to.shared.u64 t, %1; cvt.u32.u64 %0, t; }" : "=r"(a) : "l"(p));
    return a;
}
__device__ __forceinline__ void cpa16(uint32_t dst, const void* src) {
    asm volatile("cp.async.cg.shared.global [%0], [%1], 16;" :: "r"(dst), "l"(src));
}
__device__ __forceinline__ void ldsm4(uint32_t* r, uint32_t addr) {
    asm volatile("ldmatrix.sync.aligned.m8n8.x4.shared.b16 {%0,%1,%2,%3}, [%4];"
                 : "=r"(r[0]), "=r"(r[1]), "=r"(r[2]), "=r"(r[3]) : "r"(addr));
}
__device__ __forceinline__ void mma16816(float* c, const uint32_t* a,
                                         uint32_t b0, uint32_t b1) {
    asm volatile(
        "mma.sync.aligned.m16n8k16.row.col.f32.bf16.bf16.f32 "
        "{%0,%1,%2,%3}, {%4,%5,%6,%7}, {%8,%9}, {%0,%1,%2,%3};"
        : "+f"(c[0]), "+f"(c[1]), "+f"(c[2]), "+f"(c[3])
        : "r"(a[0]), "r"(a[1]), "r"(a[2]), "r"(a[3]), "r"(b0), "r"(b1));
}
// 128B-row XOR swizzle: 16B chunk index ^= (row & 7)
__device__ __forceinline__ uint32_t swz(uint32_t base, int row, int kbyte) {
    uint32_t off = (uint32_t)(row * 128 + kbyte);
    return base + (off ^ ((off >> 3) & 0x70));
}

// ---------------------------------------------------------------------------
// Kernel 1: fused prep.
// Blocks [0, 192): exact 1.5-entmax -> g_A [hi || lo].
//   Newton on g(tau)=sum relu(z-tau)^2-1 (convex => monotone from tau0=-1).
//   Each 8-lane group owns ONE column, 32 elements per lane in registers:
//   reduction = 3 shuffle levels, 1 divide per iteration (vs 5 levels x 2
//   sums x 4 cols in the warp-wide layout). Packed bf16x2 stores.
// Blocks [192, 448): split input fp32 -> g_B [hi || lo].
// ---------------------------------------------------------------------------
#define CPB 16
#define ENT_BLOCKS (NCOLS / CPB)          // 192
#define SPL_BLOCKS (BATCH * F_IN / 512)   // 256

__global__ void __launch_bounds__(128, 8)
prep_kernel(const float* __restrict__ fa,
            const float* __restrict__ input)
{
    const int tid = threadIdx.x;

    if (blockIdx.x >= ENT_BLOCKS) {
        // ---- split input: [hi || lo] rows of g_B ----
        int i = (blockIdx.x - ENT_BLOCKS) * 128 + tid;  // float4 units
        int b = i >> 6;
        int r = i & 63;                                  // k = 4*r
        float4 v = ((const float4*)input)[i];
        __nv_bfloat162 h01 = __float22bfloat162_rn(make_float2(v.x, v.y));
        __nv_bfloat162 h23 = __float22bfloat162_rn(make_float2(v.z, v.w));
        __nv_bfloat162 l01 = __float22bfloat162_rn(make_float2(
            v.x - __bfloat162float(h01.x), v.y - __bfloat162float(h01.y)));
        __nv_bfloat162 l23 = __float22bfloat162_rn(make_float2(
            v.z - __bfloat162float(h23.x), v.w - __bfloat162float(h23.y)));
        __nv_bfloat16* rowp = g_B + b * KS + r * 4;
        *(uint2*)rowp         = make_uint2(*(uint32_t*)&h01, *(uint32_t*)&h23);
        *(uint2*)(rowp + 256) = make_uint2(*(uint32_t*)&l01, *(uint32_t*)&l23);
        return;
    }

    // ---- entmax ----
    __shared__ float s[CPB][260];   // [col][k], row stride 260 (16B-aligned)

    const int c0   = blockIdx.x * CPB;
    const int lane = tid & 31;
    const int w    = tid >> 5;

    // coalesced load, transposed store (2-way STS conflicts only)
    #pragma unroll
    for (int i = 0; i < 32; i++) {
        int e = tid + i * 128;
        int c = e & 15;
        int r = e >> 4;
        s[c][r] = 0.5f * fa[r * NCOLS + c0 + c];
    }
    __syncthreads();

    const int grp = lane >> 3;      // 0..3: column group within warp
    const int gl  = lane & 7;       // lane within group
    const int col = 4 * w + grp;    // local column 0..15

    // 32 elements per lane: k = 32*m + 4*gl + t   (t = 0..3)
    float4 z4[8];
    #pragma unroll
    for (int m = 0; m < 8; m++)
        z4[m] = *(const float4*)&s[col][m * 32 + gl * 4];

    // column max: local over 32, then 3 butterfly levels within the group
    float mx = z4[0].x;
    #pragma unroll
    for (int m = 0; m < 8; m++) {
        mx = fmaxf(mx, fmaxf(fmaxf(z4[m].x, z4[m].y), fmaxf(z4[m].z, z4[m].w)));
    }
    #pragma unroll
    for (int off = 4; off > 0; off >>= 1)
        mx = fmaxf(mx, __shfl_xor_sync(0xffffffffu, mx, off));
    #pragma unroll
    for (int m = 0; m < 8; m++) {
        z4[m].x -= mx; z4[m].y -= mx; z4[m].z -= mx; z4[m].w -= mx;
    }

    // Newton: tau0 = -1 (max(z)=0); monotone from below; fast division.
    float tau = -1.0f;
    for (int it = 0; it < 12; it++) {
        float s1 = 0.0f, s2 = 0.0f;
        #pragma unroll
        for (int m = 0; m < 8; m++) {
            float d0 = fmaxf(z4[m].x - tau, 0.0f);
            float d1 = fmaxf(z4[m].y - tau, 0.0f);
            float d2 = fmaxf(z4[m].z - tau, 0.0f);
            float d3 = fmaxf(z4[m].w - tau, 0.0f);
            s1 += d0 + d1 + d2 + d3;
            s2 = fmaf(d0, d0, s2);
            s2 = fmaf(d1, d1, s2);
            s2 = fmaf(d2, d2, s2);
            s2 = fmaf(d3, d3, s2);
        }
        #pragma unroll
        for (int off = 4; off > 0; off >>= 1) {
            s1 += __shfl_xor_sync(0xffffffffu, s1, off);
            s2 += __shfl_xor_sync(0xffffffffu, s2, off);
        }
        tau += __fdividef(s2 - 1.0f, 2.0f * s1);
    }

    // emit [hi || lo] rows of g_A, packed bf16x2 (STG.64)
    __nv_bfloat16* Arow = g_A + (size_t)(c0 + col) * KS;
    #pragma unroll
    for (int m = 0; m < 8; m++) {
        float d0 = fmaxf(z4[m].x - tau, 0.0f);
        float d1 = fmaxf(z4[m].y - tau, 0.0f);
        float d2 = fmaxf(z4[m].z - tau, 0.0f);
        float d3 = fmaxf(z4[m].w - tau, 0.0f);
        float w0 = d0 * d0, w1 = d1 * d1, w2 = d2 * d2, w3 = d3 * d3;
        __nv_bfloat162 h01 = __float22bfloat162_rn(make_float2(w0, w1));
        __nv_bfloat162 h23 = __float22bfloat162_rn(make_float2(w2, w3));
        __nv_bfloat162 l01 = __float22bfloat162_rn(make_float2(
            w0 - __bfloat162float(h01.x), w1 - __bfloat162float(h01.y)));
        __nv_bfloat162 l23 = __float22bfloat162_rn(make_float2(
            w2 - __bfloat162float(h23.x), w3 - __bfloat162float(h23.y)));
        int k = m * 32 + gl * 4;
        *(uint2*)(Arow + k)       = make_uint2(*(uint32_t*)&h01, *(uint32_t*)&h23);
        *(uint2*)(Arow + 256 + k) = make_uint2(*(uint32_t*)&l01, *(uint32_t*)&l23);
    }
}

// ---------------------------------------------------------------------------
// Kernel 2: HMMA bf16 GEMM over virtual K=768:
//   kc 0-3:  A hi  x B hi      kcA = kc      kcB = kc
//   kc 4-7:  A lo  x B hi      kcA = kc      kcB = kc-4
//   kc 8-11: A hi  x B lo      kcA = kc-8    kcB = kc-4
// (drops only loA.loB ~ 2^-18). Stored arrays are [hi||lo], 512 wide.
// CTA: M=128(n) x N=64(b), 8 warps, double-buffered cp.async, XOR swizzle.
// ---------------------------------------------------------------------------
#define CK 64
#define NKC (KV / CK)    // 12

#define SA0 0
#define SA1 16384
#define SB0 32768
#define SB1 40960
#define SM_TOTAL 49152

__device__ __forceinline__ int map_kcA(int kc) { return kc < 8 ? kc : kc - 8; }
__device__ __forceinline__ int map_kcB(int kc) { return kc < 4 ? kc : kc - 4; }

__device__ __forceinline__ void load_A_chunk(uint32_t sbase, int n0, int kcA, int tid)
{
    #pragma unroll
    for (int j = 0; j < 4; j++) {
        int e = tid + j * 256;
        int row = e >> 3;
        int ch  = e & 7;
        cpa16(swz(sbase, row, ch * 16),
              g_A + (size_t)(n0 + row) * KS + kcA * CK + ch * 8);
    }
}
__device__ __forceinline__ void load_B_chunk(uint32_t sbase, int b0, int kcB, int tid)
{
    #pragma unroll
    for (int j = 0; j < 2; j++) {
        int e = tid + j * 256;
        int row = e >> 3;
        int ch  = e & 7;
        cpa16(swz(sbase, row, ch * 16),
              g_B + (size_t)(b0 + row) * KS + kcB * CK + ch * 8);
    }
}

__global__ void __launch_bounds__(256, 2)
gemm_hmma_kernel(const float* __restrict__ thr,
                 const float* __restrict__ ltemp)
{
    extern __shared__ char smem[];
    const uint32_t sb = smem_u32(smem);
    const int tid  = threadIdx.x;
    const int lane = tid & 31;
    const int wid  = tid >> 5;
    const int wm   = wid >> 1;
    const int wn   = wid & 1;

    const int n0 = blockIdx.x * 128;
    const int b0 = blockIdx.y * 64;

    const uint32_t sA[2] = {sb + SA0, sb + SA1};
    const uint32_t sB[2] = {sb + SB0, sb + SB1};

    float acc[2][4][4];
    #pragma unroll
    for (int mi = 0; mi < 2; mi++)
        #pragma unroll
        for (int ni = 0; ni < 4; ni++)
            #pragma unroll
            for (int q = 0; q < 4; q++) acc[mi][ni][q] = 0.0f;

    load_A_chunk(sA[0], n0, map_kcA(0), tid);
    load_B_chunk(sB[0], b0, map_kcB(0), tid);
    asm volatile("cp.async.commit_group;");

    const int lane15 = lane & 15;
    const int khalf  = (lane >> 4) * 16;

    int buf = 0;
    for (int kc = 0; kc < NKC; kc++) {
        if (kc + 1 < NKC) {
            load_A_chunk(sA[buf ^ 1], n0, map_kcA(kc + 1), tid);
            load_B_chunk(sB[buf ^ 1], b0, map_kcB(kc + 1), tid);
            asm volatile("cp.async.commit_group;");
            asm volatile("cp.async.wait_group 1;");
        } else {
            asm volatile("cp.async.wait_group 0;");
        }
        __syncthreads();

        #pragma unroll
        for (int ks = 0; ks < 4; ks++) {
            const int kbyte = ks * 32 + khalf;
            uint32_t a0[4], a1[4], bq0[4], bq1[4];
            ldsm4(a0,  swz(sA[buf], wm * 32 + lane15,      kbyte));
            ldsm4(a1,  swz(sA[buf], wm * 32 + 16 + lane15, kbyte));
            ldsm4(bq0, swz(sB[buf], wn * 32 + lane15,      kbyte));
            ldsm4(bq1, swz(sB[buf], wn * 32 + 16 + lane15, kbyte));

            mma16816(acc[0][0], a0, bq0[0], bq0[2]);
            mma16816(acc[0][1], a0, bq0[1], bq0[3]);
            mma16816(acc[0][2], a0, bq1[0], bq1[2]);
            mma16816(acc[0][3], a0, bq1[1], bq1[3]);
            mma16816(acc[1][0], a1, bq0[0], bq0[2]);
            mma16816(acc[1][1], a1, bq0[1], bq0[3]);
            mma16816(acc[1][2], a1, bq1[0], bq1[2]);
            mma16816(acc[1][3], a1, bq1[1], bq1[3]);
        }
        __syncthreads();
        buf ^= 1;
    }

    const int qr = lane >> 2;
    const int qc = (lane & 3) * 2;
    #pragma unroll
    for (int mi = 0; mi < 2; mi++) {
        const int nr0 = n0 + wm * 32 + mi * 16 + qr;
        const int nr1 = nr0 + 8;
        const int t0 = nr0 / DEPTH, d0 = nr0 % DEPTH;
        const int t1 = nr1 / DEPTH, d1 = nr1 % DEPTH;
        const float th0 = thr[t0 * DEPTH + d0];
        const float sc0 = expf(-ltemp[t0 * DEPTH + d0]);
        const float th1 = thr[t1 * DEPTH + d1];
        const float sc1 = expf(-ltemp[t1 * DEPTH + d1]);
        #pragma unroll
        for (int ni = 0; ni < 4; ni++) {
            const int bc = b0 + wn * 32 + ni * 8 + qc;
            float2 v0, v1;
            v0.x = (acc[mi][ni][0] - th0) * sc0;
            v0.y = (acc[mi][ni][1] - th0) * sc0;
            v1.x = (acc[mi][ni][2] - th1) * sc1;
            v1.y = (acc[mi][ni][3] - th1) * sc1;
            *(float2*)&g_tl[(size_t)nr0 * BATCH + bc] = v0;
            *(float2*)&g_tl[(size_t)nr1 * BATCH + bc] = v1;
        }
    }
}

// ---------------------------------------------------------------------------
// Kernel 3: one (tree, batch) pair per thread. Block = 8 trees x 32 batches.
// ---------------------------------------------------------------------------
#define TT 8    // trees per block
#define BB 32   // batches per block

__global__ void __launch_bounds__(256, 4)
leaf_kernel(const float* __restrict__ response,  // [512][3][64]
            float* __restrict__ out)             // [512][1536]
{
    __shared__ float4 rsp4[TT * 48];
    __shared__ float  sout[BB][TT * 3 + 3];

    const int t0   = blockIdx.x * TT;
    const int b0   = blockIdx.y * BB;
    const int tid  = threadIdx.x;
    const int lane = tid & 31;
    const int w    = tid >> 5;

    for (int i = tid; i < TT * 48; i += 256)
        rsp4[i] = ((const float4*)response)[(size_t)t0 * 48 + i];
    __syncthreads();

    const int t = t0 + w;
    const int b = b0 + lane;

    float a[DEPTH], bb[DEPTH];
    #pragma unroll
    for (int d = 0; d < DEPTH; d++) {
        float v = g_tl[(size_t)(t * DEPTH + d) * BATCH + b];
        float x = 0.5f * v;
        a[d]  = fminf(fmaxf(0.5f + x, -0.5f), 1.5f);
        bb[d] = fminf(fmaxf(0.5f - x, -0.5f), 1.5f);
    }

    float w8[8];
    w8[0] = 1.0f;
    #pragma unroll
    for (int d = 0; d < 3; d++) {
        const int sz = 1 << d;
        #pragma unroll
        for (int i = sz - 1; i >= 0; i--) {
            w8[i + sz] = w8[i] * bb[d];
            w8[i]      = w8[i] * a[d];
        }
    }
    float q8[8];
    q8[0] = 1.0f;
    #pragma unroll
    for (int e = 0; e < 3; e++) {
        const int sz = 1 << e;
        #pragma unroll
        for (int i = sz - 1; i >= 0; i--) {
            q8[i + sz] = q8[i] * bb[3 + e];
            q8[i]      = q8[i] * a[3 + e];
        }
    }

    const float4* rp = &rsp4[w * 48];
    float o0 = 0.0f, o1 = 0.0f, o2 = 0.0f;
    #pragma unroll
    for (int j = 0; j < 8; j++) {
        float4 r00 = rp[j * 2],      r01 = rp[j * 2 + 1];
        float4 r10 = rp[16 + j * 2], r11 = rp[16 + j * 2 + 1];
        float4 r20 = rp[32 + j * 2], r21 = rp[32 + j * 2 + 1];
        float s0 = w8[0]*r00.x + w8[1]*r00.y + w8[2]*r00.z + w8[3]*r00.w
                 + w8[4]*r01.x + w8[5]*r01.y + w8[6]*r01.z + w8[7]*r01.w;
        float s1 = w8[0]*r10.x + w8[1]*r10.y + w8[2]*r10.z + w8[3]*r10.w
                 + w8[4]*r11.x + w8[5]*r11.y + w8[6]*r11.z + w8[7]*r11.w;
        float s2 = w8[0]*r20.x + w8[1]*r20.y + w8[2]*r20.z + w8[3]*r20.w
                 + w8[4]*r21.x + w8[5]*r21.y + w8[6]*r21.z + w8[7]*r21.w;
        o0 = fmaf(q8[j], s0, o0);
        o1 = fmaf(q8[j], s1, o1);
        o2 = fmaf(q8[j], s2, o2);
    }

    sout[lane][w * 3 + 0] = o0;
    sout[lane][w * 3 + 1] = o1;
    sout[lane][w * 3 + 2] = o2;
    __syncthreads();

    if (tid < (BB * TT * 3) / 4) {
        int row = tid / 6;
        int col = tid % 6;
        float4 v;
        v.x = sout[row][col * 4 + 0];
        v.y = sout[row][col * 4 + 1];
        v.z = sout[row][col * 4 + 2];
        v.w = sout[row][col * 4 + 3];
        *(float4*)&out[(size_t)(b0 + row) * (NTREES * TDIM) + t0 * 3 + col * 4] = v;
    }
}

// ---------------------------------------------------------------------------
extern "C" void kernel_launch(void* const* d_in, const int* in_sizes, int n_in,
                              void* d_out, int out_size)
{
    const float* input    = (const float*)d_in[0];  // [512][256]
    const float* fa       = (const float*)d_in[1];  // [256][3072]
    const float* thr      = (const float*)d_in[2];  // [512][6]
    const float* ltemp    = (const float*)d_in[3];  // [512][6]
    const float* response = (const float*)d_in[4];  // [512][3][64]
    float* out = (float*)d_out;                     // [512][1536]

    cudaFuncSetAttribute(gemm_hmma_kernel,
                         cudaFuncAttributeMaxDynamicSharedMemorySize, SM_TOTAL);

    prep_kernel<<<ENT_BLOCKS + SPL_BLOCKS, 128>>>(fa, input);

    dim3 g2(NCOLS / 128, BATCH / 64);
    gemm_hmma_kernel<<<g2, 256, SM_TOTAL>>>(thr, ltemp);

    dim3 g3(NTREES / TT, BATCH / BB);
    leaf_kernel<<<g3, 256>>>(response, out);
}